// round 13
// baseline (speedup 1.0000x reference)
#include <cuda_runtime.h>
#include <cuda_bf16.h>
#include <math.h>
#include <stdint.h>

#define NR 8192
#define CD 1024
#define HD 256
#define FGDIM 64
#define CLDIM 128
#define NSPL_FG 4
#define NSPL_CLS 4
#define CSBLK 256   // class-sum partial blocks (32 rows each)

// ---------------- device scratch (no allocs allowed) ----------------
__device__ __nv_bfloat16 g_Xh[NR * CD];
__device__ __nv_bfloat16 g_Xl[NR * CD];
__device__ __nv_bfloat16 g_W1fh[HD * CD];
__device__ __nv_bfloat16 g_W1fl[HD * CD];
__device__ __nv_bfloat16 g_W1ch[HD * CD];
__device__ __nv_bfloat16 g_W1cl[HD * CD];
__device__ __nv_bfloat16 g_W2fh[FGDIM * HD];
__device__ __nv_bfloat16 g_W2fl[FGDIM * HD];
__device__ __nv_bfloat16 g_W2ch[CLDIM * HD];
__device__ __nv_bfloat16 g_W2cl[CLDIM * HD];
__device__ __nv_bfloat16 g_Hfh[NR * HD];
__device__ __nv_bfloat16 g_Hfl[NR * HD];
__device__ __nv_bfloat16 g_Hch[NR * HD];
__device__ __nv_bfloat16 g_Hcl[NR * HD];
__device__ float g_Zc[NR * CLDIM];            // CLS fp32 (original row order)
__device__ __nv_bfloat16 g_Zfh[NR * FGDIM];
__device__ __nv_bfloat16 g_Zch[NR * CLDIM];
__device__ float g_pfg[NSPL_FG * NR * 2];     // per split, per row: denom, numer
__device__ float g_pcl[NSPL_CLS * NR];        // per split, per row: denom
__device__ float g_Sp[20 * CSBLK * CLDIM];    // per-class per-block partial sums
__device__ float g_S[20 * CLDIM];
__device__ float g_sp[NR];                    // per-row sum_pos (CLS)
__device__ float g_eiif[NR];                  // per-row self exp (FG, hi*hi)
__device__ float g_eiic[NR];                  // per-row self exp (CLS, hi*hi)
__device__ float g_ssc[NR];                   // per-row ||z||^2 (CLS)
__device__ int   g_lbl[NR];
__device__ float g_fgf[NR];
__device__ float g_vld[NR];
__device__ float g_wgt[NR];

// ---------------- helpers ----------------
__device__ __forceinline__ uint32_t smem_u32(const void* p) {
    uint32_t a;
    asm("{ .reg .u64 t; cvta.to.shared.u64 t, %1; cvt.u32.u64 %0, t; }" : "=r"(a) : "l"(p));
    return a;
}

#define LDSM4(r, addr) \
    asm volatile("ldmatrix.sync.aligned.m8n8.x4.shared.b16 {%0,%1,%2,%3}, [%4];" \
        : "=r"((r)[0]), "=r"((r)[1]), "=r"((r)[2]), "=r"((r)[3]) : "r"(addr))

#define MMA16816(d, a, b0, b1) \
    asm volatile("mma.sync.aligned.m16n8k16.row.col.f32.bf16.bf16.f32 " \
        "{%0,%1,%2,%3},{%4,%5,%6,%7},{%8,%9},{%0,%1,%2,%3};" \
        : "+f"((d)[0]), "+f"((d)[1]), "+f"((d)[2]), "+f"((d)[3]) \
        : "r"((a)[0]), "r"((a)[1]), "r"((a)[2]), "r"((a)[3]), "r"(b0), "r"(b1))

// ---------------- packed f32x2 ops ----------------
__device__ __forceinline__ uint64_t pk2(float a, float b) {
    uint64_t r; asm("mov.b64 %0, {%1, %2};" : "=l"(r) : "f"(a), "f"(b)); return r;
}
__device__ __forceinline__ void upk2(uint64_t v, float& a, float& b) {
    asm("mov.b64 {%0, %1}, %2;" : "=f"(a), "=f"(b) : "l"(v));
}
__device__ __forceinline__ uint64_t fma2(uint64_t a, uint64_t b, uint64_t c) {
    uint64_t d; asm("fma.rn.f32x2 %0, %1, %2, %3;" : "=l"(d) : "l"(a), "l"(b), "l"(c)); return d;
}
__device__ __forceinline__ uint64_t add2(uint64_t a, uint64_t b) {
    uint64_t d; asm("add.rn.f32x2 %0, %1, %2;" : "=l"(d) : "l"(a), "l"(b)); return d;
}
__device__ __forceinline__ uint64_t mul2(uint64_t a, uint64_t b) {
    uint64_t d; asm("mul.rn.f32x2 %0, %1, %2;" : "=l"(d) : "l"(a), "l"(b)); return d;
}

// packed exp(5x): range reduce + cubic 2^f on [-0.5, 0.5]
__device__ __forceinline__ uint64_t fexp5_2(uint64_t x2) {
    const float KE = 7.2134752044448169f;   // 5 * log2(e)
    const float SH = 12582912.0f;           // 1.5 * 2^23
    const uint64_t KE2 = pk2(KE, KE);
    const uint64_t SH2 = pk2(SH, SH);
    const uint64_t N12 = pk2(-1.0f, -1.0f);
    uint64_t z2 = fma2(x2, KE2, SH2);
    float zl, zh; upk2(z2, zl, zh);
    int e0 = (__float_as_int(zl) - 0x4B3FFF81) << 23;
    int e1 = (__float_as_int(zh) - 0x4B3FFF81) << 23;
    uint64_t nr2 = fma2(z2, N12, SH2);
    uint64_t f2 = fma2(x2, KE2, nr2);
    uint64_t p = pk2(0.0559174f, 0.0559174f);
    p = fma2(p, f2, pk2(0.2426311f, 0.2426311f));
    p = fma2(p, f2, pk2(0.6930790f, 0.6930790f));
    p = fma2(p, f2, pk2(0.9999247f, 0.9999247f));
    return mul2(p, pk2(__int_as_float(e0), __int_as_float(e1)));
}

// scalar exp(5x), degree-4
__device__ __forceinline__ float fexp5(float x) {
    const float KE = 7.2134752044448169f;
    const float SH = 12582912.0f;
    float z = fmaf(x, KE, SH);
    int   ei = __float_as_int(z);
    float r = z - SH;
    float f = fmaf(x, KE, -r);
    float p = 9.6181291076284771e-3f;
    p = fmaf(p, f, 5.5504108664821580e-2f);
    p = fmaf(p, f, 2.4022650695910071e-1f);
    p = fmaf(p, f, 6.9314718055994531e-1f);
    p = fmaf(p, f, 1.0f);
    return p * __int_as_float((ei - 0x4B400000 + 127) << 23);
}

// ---------------- merged prep + hi/lo conversions (one launch) ----------------
#define SEG_X   2097152
#define SEG_W1F 2162688
#define SEG_W1C 2228224
#define SEG_W2F 2232320
#define SEG_W2C 2240512
#define CONV_BLKS 8752

__global__ void prep_conv_kernel(const float* __restrict__ roi,
                                 const float* __restrict__ w1f, const float* __restrict__ w1c,
                                 const float* __restrict__ w2f, const float* __restrict__ w2c,
                                 const int* __restrict__ lraw, const float* __restrict__ ious) {
    if (blockIdx.x >= CONV_BLKS) {
        int i = (blockIdx.x - CONV_BLKS) * 256 + threadIdx.x;
        bool is64 = true;
        #pragma unroll 1
        for (int p = 0; p < 32; ++p) {
            int lo = lraw[2 * p], hi = lraw[2 * p + 1];
            bool ok = (hi == 0 && lo >= 0) || (hi == -1 && lo < 0);
            if (!ok) { is64 = false; break; }
        }
        int l = is64 ? (int)(((const long long*)lraw)[i]) : lraw[i];
        g_lbl[i] = l;
        g_fgf[i] = (l > 0) ? 1.0f : 0.0f;
        g_vld[i] = (l != -1) ? 1.0f : 0.0f;
        float u = ious[i];
        g_wgt[i] = (u > 0.5f) ? u : 0.0f;
        return;
    }
    int i = blockIdx.x * 256 + threadIdx.x;
    const float* s; __nv_bfloat16 *h, *l; int base;
    if (i < SEG_X)        { s = roi; h = g_Xh;   l = g_Xl;   base = 0; }
    else if (i < SEG_W1F) { s = w1f; h = g_W1fh; l = g_W1fl; base = SEG_X; }
    else if (i < SEG_W1C) { s = w1c; h = g_W1ch; l = g_W1cl; base = SEG_W1F; }
    else if (i < SEG_W2F) { s = w2f; h = g_W2fh; l = g_W2fl; base = SEG_W1C; }
    else                  { s = w2c; h = g_W2ch; l = g_W2cl; base = SEG_W2F; }
    int j = i - base;
    float4 v = ((const float4*)s)[j];
    __nv_bfloat162 h0, h1, l0, l1;
    h0.x = __float2bfloat16(v.x); h0.y = __float2bfloat16(v.y);
    h1.x = __float2bfloat16(v.z); h1.y = __float2bfloat16(v.w);
    l0.x = __float2bfloat16(v.x - __bfloat162float(h0.x));
    l0.y = __float2bfloat16(v.y - __bfloat162float(h0.y));
    l1.x = __float2bfloat16(v.z - __bfloat162float(h1.x));
    l1.y = __float2bfloat16(v.w - __bfloat162float(h1.y));
    ((__nv_bfloat162*)h)[j * 2] = h0; ((__nv_bfloat162*)h)[j * 2 + 1] = h1;
    ((__nv_bfloat162*)l)[j * 2] = l0; ((__nv_bfloat162*)l)[j * 2 + 1] = l1;
}

// ---------------- cp.async bf16 tile loader (BK=64, padded stride 144B) ----------------
__device__ __forceinline__ void ld_tile64(uint32_t dst, const __nv_bfloat16* __restrict__ src,
                                          int rows, int K, int tid) {
    #pragma unroll 4
    for (int i = tid; i < rows * 8; i += 256) {
        int r = i >> 3, c = i & 7;
        asm volatile("cp.async.cg.shared.global [%0], [%1], 16;"
                     :: "r"(dst + r * 144 + c * 16), "l"(src + (size_t)r * K + c * 8) : "memory");
    }
}

// ---------------- layer-1 MMA GEMM (3-chain, relu + hi/lo split out) ----------------
__global__ __launch_bounds__(256) void mma_gemm1(
    const float* __restrict__ bias0, const float* __restrict__ bias1) {
    constexpr int BN = 128, SA = 144;
    constexpr int ATS = 128 * SA;
    constexpr int BTS = BN * SA;
    constexpr int STG = 2 * ATS + 2 * BTS;
    constexpr int NG = BN / 32, NF = 2 * NG;
    constexpr int N = HD, K = CD;

    extern __shared__ char smem[];
    uint32_t sb = smem_u32(smem);
    const int tid = threadIdx.x, wid = tid >> 5, lane = tid & 31;
    const int wm = wid & 3, wn = wid >> 2;
    const int z = blockIdx.z;
    const int bm = blockIdx.y * 128, bn = blockIdx.x * BN;

    const __nv_bfloat16* Ah = g_Xh;
    const __nv_bfloat16* Al = g_Xl;
    const __nv_bfloat16* Wh = z ? g_W1ch : g_W1fh;
    const __nv_bfloat16* Wl = z ? g_W1cl : g_W1fl;
    const float* bias = z ? bias1 : bias0;
    __nv_bfloat16* oh = z ? g_Hch : g_Hfh;
    __nv_bfloat16* ol = z ? g_Hcl : g_Hfl;

    const int KC = K >> 6;

    ld_tile64(sb, Ah + (size_t)bm * K, 128, K, tid);
    ld_tile64(sb + ATS, Al + (size_t)bm * K, 128, K, tid);
    ld_tile64(sb + 2 * ATS, Wh + (size_t)bn * K, BN, K, tid);
    ld_tile64(sb + 2 * ATS + BTS, Wl + (size_t)bn * K, BN, K, tid);
    asm volatile("cp.async.commit_group;" ::: "memory");

    float acc[2][NF][4];
    #pragma unroll
    for (int ma = 0; ma < 2; ++ma)
        #pragma unroll
        for (int nf = 0; nf < NF; ++nf)
            #pragma unroll
            for (int e = 0; e < 4; ++e) acc[ma][nf][e] = 0.0f;

    const uint32_t a_off = (uint32_t)((wm * 32 + (lane & 15)) * SA + (lane >> 4) * 16);
    const uint32_t b_off = (uint32_t)((wn * (BN / 2) + ((lane >> 4) << 3) + (lane & 7)) * SA + ((lane >> 3) & 1) * 16);

    for (int kc = 0; kc < KC; ++kc) {
        const uint32_t cur = sb + (kc & 1) * STG;
        if (kc + 1 < KC) {
            const uint32_t nxt = sb + ((kc + 1) & 1) * STG;
            const int ko = (kc + 1) * 64;
            ld_tile64(nxt, Ah + (size_t)bm * K + ko, 128, K, tid);
            ld_tile64(nxt + ATS, Al + (size_t)bm * K + ko, 128, K, tid);
            ld_tile64(nxt + 2 * ATS, Wh + (size_t)bn * K + ko, BN, K, tid);
            ld_tile64(nxt + 2 * ATS + BTS, Wl + (size_t)bn * K + ko, BN, K, tid);
            asm volatile("cp.async.commit_group;" ::: "memory");
            asm volatile("cp.async.wait_group 1;" ::: "memory");
        } else {
            asm volatile("cp.async.wait_group 0;" ::: "memory");
        }
        __syncthreads();

        #pragma unroll
        for (int ks = 0; ks < 4; ++ks) {
            const uint32_t kb = ks * 32;
            uint32_t a_h[2][4], a_l[2][4], b_h[NG][4], b_l[NG][4];
            #pragma unroll
            for (int ma = 0; ma < 2; ++ma) {
                LDSM4(a_h[ma], cur + a_off + ma * 16 * SA + kb);
                LDSM4(a_l[ma], cur + ATS + a_off + ma * 16 * SA + kb);
            }
            #pragma unroll
            for (int g = 0; g < NG; ++g) {
                LDSM4(b_h[g], cur + 2 * ATS + b_off + g * 16 * SA + kb);
                LDSM4(b_l[g], cur + 2 * ATS + BTS + b_off + g * 16 * SA + kb);
            }
            #pragma unroll
            for (int ma = 0; ma < 2; ++ma)
                #pragma unroll
                for (int g = 0; g < NG; ++g) {
                    MMA16816(acc[ma][2 * g],     a_h[ma], b_h[g][0], b_h[g][1]);
                    MMA16816(acc[ma][2 * g + 1], a_h[ma], b_h[g][2], b_h[g][3]);
                    MMA16816(acc[ma][2 * g],     a_h[ma], b_l[g][0], b_l[g][1]);
                    MMA16816(acc[ma][2 * g + 1], a_h[ma], b_l[g][2], b_l[g][3]);
                    MMA16816(acc[ma][2 * g],     a_l[ma], b_h[g][0], b_h[g][1]);
                    MMA16816(acc[ma][2 * g + 1], a_l[ma], b_h[g][2], b_h[g][3]);
                }
        }
        __syncthreads();
    }

    #pragma unroll
    for (int ma = 0; ma < 2; ++ma)
        #pragma unroll
        for (int nf = 0; nf < NF; ++nf)
            #pragma unroll
            for (int rp = 0; rp < 2; ++rp) {
                const int r = bm + wm * 32 + ma * 16 + rp * 8 + (lane >> 2);
                const int c = bn + wn * (BN / 2) + nf * 8 + (lane & 3) * 2;
                float2 bb = *(const float2*)(bias + c);
                float v0 = fmaxf(acc[ma][nf][rp * 2 + 0] + bb.x, 0.0f);
                float v1 = fmaxf(acc[ma][nf][rp * 2 + 1] + bb.y, 0.0f);
                __nv_bfloat162 hv, lv;
                hv.x = __float2bfloat16(v0); hv.y = __float2bfloat16(v1);
                lv.x = __float2bfloat16(v0 - __bfloat162float(hv.x));
                lv.y = __float2bfloat16(v1 - __bfloat162float(hv.y));
                *(__nv_bfloat162*)(oh + (size_t)r * N + c) = hv;
                *(__nv_bfloat162*)(ol + (size_t)r * N + c) = lv;
            }
}

// ---------------- layer-2 body: GEMM + fused normalize + hi-split + eii/ss ----------------
template<int BN>
__device__ __forceinline__ void gemm2_body(
    const __nv_bfloat16* __restrict__ Ah, const __nv_bfloat16* __restrict__ Al,
    const __nv_bfloat16* __restrict__ Wh, const __nv_bfloat16* __restrict__ Wl,
    const float* __restrict__ bias,
    float* __restrict__ Zout, __nv_bfloat16* __restrict__ Oh,
    float* __restrict__ eii, float* __restrict__ ssout,
    int bm, char* smem) {
    constexpr int SA = 144;
    constexpr int ATS = 128 * SA;
    constexpr int BTS = BN * SA;
    constexpr int STG = 2 * ATS + 2 * BTS;
    constexpr int NG = BN / 32, NF = 2 * NG;
    constexpr int K = HD;
    constexpr int ZS = BN + 4;

    uint32_t sb = smem_u32(smem);
    float* zbuf = (float*)smem;
    const int tid = threadIdx.x, wid = tid >> 5, lane = tid & 31;
    const int wm = wid & 3, wn = wid >> 2;

    const int KC = K >> 6;

    ld_tile64(sb, Ah + (size_t)bm * K, 128, K, tid);
    ld_tile64(sb + ATS, Al + (size_t)bm * K, 128, K, tid);
    ld_tile64(sb + 2 * ATS, Wh, BN, K, tid);
    ld_tile64(sb + 2 * ATS + BTS, Wl, BN, K, tid);
    asm volatile("cp.async.commit_group;" ::: "memory");

    float acc[2][NF][4];
    #pragma unroll
    for (int ma = 0; ma < 2; ++ma)
        #pragma unroll
        for (int nf = 0; nf < NF; ++nf)
            #pragma unroll
            for (int e = 0; e < 4; ++e) acc[ma][nf][e] = 0.0f;

    const uint32_t a_off = (uint32_t)((wm * 32 + (lane & 15)) * SA + (lane >> 4) * 16);
    const uint32_t b_off = (uint32_t)((wn * (BN / 2) + ((lane >> 4) << 3) + (lane & 7)) * SA + ((lane >> 3) & 1) * 16);

    for (int kc = 0; kc < KC; ++kc) {
        const uint32_t cur = sb + (kc & 1) * STG;
        if (kc + 1 < KC) {
            const uint32_t nxt = sb + ((kc + 1) & 1) * STG;
            const int ko = (kc + 1) * 64;
            ld_tile64(nxt, Ah + (size_t)bm * K + ko, 128, K, tid);
            ld_tile64(nxt + ATS, Al + (size_t)bm * K + ko, 128, K, tid);
            ld_tile64(nxt + 2 * ATS, Wh + ko, BN, K, tid);
            ld_tile64(nxt + 2 * ATS + BTS, Wl + ko, BN, K, tid);
            asm volatile("cp.async.commit_group;" ::: "memory");
            asm volatile("cp.async.wait_group 1;" ::: "memory");
        } else {
            asm volatile("cp.async.wait_group 0;" ::: "memory");
        }
        __syncthreads();

        #pragma unroll
        for (int ks = 0; ks < 4; ++ks) {
            const uint32_t kb = ks * 32;
            uint32_t a_h[2][4], a_l[2][4], b_h[NG][4], b_l[NG][4];
            #pragma unroll
            for (int ma = 0; ma < 2; ++ma) {
                LDSM4(a_h[ma], cur + a_off + ma * 16 * SA + kb);
                LDSM4(a_l[ma], cur + ATS + a_off + ma * 16 * SA + kb);
            }
            #pragma unroll
            for (int g = 0; g < NG; ++g) {
                LDSM4(b_h[g], cur + 2 * ATS + b_off + g * 16 * SA + kb);
                LDSM4(b_l[g], cur + 2 * ATS + BTS + b_off + g * 16 * SA + kb);
            }
            #pragma unroll
            for (int ma = 0; ma < 2; ++ma)
                #pragma unroll
                for (int g = 0; g < NG; ++g) {
                    MMA16816(acc[ma][2 * g],     a_h[ma], b_h[g][0], b_h[g][1]);
                    MMA16816(acc[ma][2 * g + 1], a_h[ma], b_h[g][2], b_h[g][3]);
                    MMA16816(acc[ma][2 * g],     a_h[ma], b_l[g][0], b_l[g][1]);
                    MMA16816(acc[ma][2 * g + 1], a_h[ma], b_l[g][2], b_l[g][3]);
                    MMA16816(acc[ma][2 * g],     a_l[ma], b_h[g][0], b_h[g][1]);
                    MMA16816(acc[ma][2 * g + 1], a_l[ma], b_h[g][2], b_h[g][3]);
                }
        }
        __syncthreads();
    }

    #pragma unroll
    for (int ma = 0; ma < 2; ++ma)
        #pragma unroll
        for (int nf = 0; nf < NF; ++nf)
            #pragma unroll
            for (int rp = 0; rp < 2; ++rp) {
                const int r = wm * 32 + ma * 16 + rp * 8 + (lane >> 2);
                const int c = wn * (BN / 2) + nf * 8 + (lane & 3) * 2;
                float2 bb = *(const float2*)(bias + c);
                zbuf[r * ZS + c] = acc[ma][nf][rp * 2 + 0] + bb.x;
                zbuf[r * ZS + c + 1] = acc[ma][nf][rp * 2 + 1] + bb.y;
            }
    __syncthreads();

    constexpr int CE = BN / 32;
    for (int rr = 0; rr < 16; ++rr) {
        const int r = wid * 16 + rr;
        const int grow = bm + r;
        float v[CE];
        float ss = 0.0f;
        #pragma unroll
        for (int q = 0; q < CE; ++q) { v[q] = zbuf[r * ZS + lane + q * 32]; ss += v[q] * v[q]; }
        #pragma unroll
        for (int o = 16; o; o >>= 1) ss += __shfl_xor_sync(0xffffffffu, ss, o);
        const float inv = 1.0f / fmaxf(sqrtf(ss), 1e-8f);
        float hh = 0.0f;
        #pragma unroll
        for (int q = 0; q < CE; ++q) {
            float zv = v[q] * inv;
            if (Zout) Zout[(size_t)grow * BN + lane + q * 32] = zv;
            __nv_bfloat16 h = __float2bfloat16(zv);
            Oh[(size_t)grow * BN + lane + q * 32] = h;
            float hf = __bfloat162float(h);
            hh = fmaf(hf, hf, hh);
        }
        #pragma unroll
        for (int o = 16; o; o >>= 1) hh += __shfl_xor_sync(0xffffffffu, hh, o);
        if (lane == 0) {
            eii[grow] = fexp5(hh);
            if (ssout) ssout[grow] = ss * inv * inv;
        }
    }
}

__global__ __launch_bounds__(256) void mma_gemm2_all(
    const float* __restrict__ b2f, const float* __restrict__ b2c) {
    extern __shared__ char smem[];
    if (blockIdx.x < 64)
        gemm2_body<FGDIM>(g_Hfh, g_Hfl, g_W2fh, g_W2fl, b2f,
                          nullptr, g_Zfh, g_eiif, nullptr,
                          blockIdx.x * 128, smem);
    else
        gemm2_body<CLDIM>(g_Hch, g_Hcl, g_W2ch, g_W2cl, b2c,
                          g_Zc, g_Zch, g_eiic, g_ssc,
                          (blockIdx.x - 64) * 128, smem);
}

// ---------------- per-class z sums: row-pass with smem accumulator, 256 blocks ----------------
__global__ void class_sum1_kernel() {     // grid CSBLK (256), block CLDIM (128), 32 rows each
    __shared__ float sh[20][CLDIM];
    const int d = threadIdx.x;
    #pragma unroll
    for (int c = 0; c < 20; ++c) sh[c][d] = 0.0f;
    const int i0 = blockIdx.x * (NR / CSBLK);
    // prefetch-decoupled loop: LDG for row i+1 issued before row i's smem RMW
    int   lc = g_lbl[i0];
    float vc = g_Zc[(size_t)i0 * CLDIM + d];
    #pragma unroll 1
    for (int i = i0; i < i0 + NR / CSBLK - 1; ++i) {
        int   ln = g_lbl[i + 1];
        float vn = g_Zc[(size_t)(i + 1) * CLDIM + d];
        if (lc > 0) sh[lc - 1][d] += vc;
        lc = ln; vc = vn;
    }
    if (lc > 0) sh[lc - 1][d] += vc;
    #pragma unroll
    for (int c = 0; c < 20; ++c)
        g_Sp[((size_t)c * CSBLK + blockIdx.x) * CLDIM + d] = sh[c][d];
}
__global__ void class_sum2_kernel() {     // grid 20, block CLDIM
    float s = 0.0f;
    #pragma unroll 8
    for (int g = 0; g < CSBLK; ++g)
        s += g_Sp[((size_t)blockIdx.x * CSBLK + g) * CLDIM + threadIdx.x];
    g_S[blockIdx.x * CLDIM + threadIdx.x] = s;
}

// ---------------- per-row sum_pos for CLS (warp per row) ----------------
__global__ void row_sp_kernel() {
    int row = blockIdx.x * 8 + (threadIdx.x >> 5);
    int lane = threadIdx.x & 31;
    int l = g_lbl[row];
    const float* S = g_S + (l > 0 ? (l - 1) : 0) * CLDIM;
    float sd = 0.0f;
    #pragma unroll
    for (int c = lane; c < CLDIM; c += 32)
        sd += g_Zc[(size_t)row * CLDIM + c] * S[c];
    #pragma unroll
    for (int o = 16; o; o >>= 1) sd += __shfl_xor_sync(0xffffffffu, sd, o);
    if (lane == 0) g_sp[row] = 5.0f * (sd - g_ssc[row]);
}

// ---------------- cp.async tile loader for sim (full K resident) ----------------
template<int KD>
__device__ __forceinline__ void load_tile(uint32_t dst, const __nv_bfloat16* __restrict__ src, int tid) {
    constexpr int CPR = KD / 8;
    constexpr int SA = KD * 2 + 16;
    #pragma unroll
    for (int i = tid; i < 128 * CPR; i += 256) {
        int r = i / CPR, c = i % CPR;
        asm volatile("cp.async.cg.shared.global [%0], [%1], 16;"
                     :: "r"(dst + r * SA + c * 16), "l"(src + (size_t)r * KD + c * 8) : "memory");
    }
}

// ---------------- sim body (1-chain hi*hi, flag-load packed epilogue) ----------------
template<int KD, bool CLS, int NSPLT>
__device__ __forceinline__ void sim_body(int bx, int by, char* smem) {
    constexpr int SA = KD * 2 + 16;
    constexpr int TSZ = 128 * SA;
    constexpr int SLAB = NR / NSPLT;
    constexpr int TCOLS = SLAB / 128;
    constexpr int KSTEPS = KD / 16;
    constexpr int B_OFF = TSZ;

    uint32_t sb = smem_u32(smem);
    const int tid = threadIdx.x, wid = tid >> 5, lane = tid & 31;
    const int wm = wid & 3, wn = wid >> 2;
    const int bm = bx * 128;
    const int c0 = by * SLAB;
    const __nv_bfloat16* Zh = CLS ? g_Zch : g_Zfh;
    const float* flg = CLS ? g_vld : g_fgf;

    load_tile<KD>(sb, Zh + (size_t)bm * KD, tid);
    load_tile<KD>(sb + B_OFF, Zh + (size_t)c0 * KD, tid);
    asm volatile("cp.async.commit_group;" ::: "memory");

    uint64_t dn2[2][2] = {{0ull, 0ull}, {0ull, 0ull}};
    uint64_t x12[2][2] = {{0ull, 0ull}, {0ull, 0ull}};

    const uint32_t a_off = (uint32_t)((wm * 32 + (lane & 15)) * SA + (lane >> 4) * 16);
    const uint32_t b_off = (uint32_t)((wn * 64 + ((lane >> 4) << 3) + (lane & 7)) * SA + ((lane >> 3) & 1) * 16);

    float acc[2][8][4];
    #pragma unroll
    for (int ma = 0; ma < 2; ++ma)
        #pragma unroll
        for (int na = 0; na < 8; ++na)
            #pragma unroll
            for (int e = 0; e < 4; ++e) acc[ma][na][e] = 0.0f;

    asm volatile("cp.async.wait_group 0;" ::: "memory");
    __syncthreads();

    for (int t = 0; t < TCOLS; ++t) {
        const uint32_t bcur = sb + B_OFF + (t & 1) * TSZ;
        if (t + 1 < TCOLS) {
            load_tile<KD>(sb + B_OFF + ((t + 1) & 1) * TSZ,
                          Zh + (size_t)(c0 + (t + 1) * 128) * KD, tid);
            asm volatile("cp.async.commit_group;" ::: "memory");
        }

        #pragma unroll
        for (int ks = 0; ks < KSTEPS; ++ks) {
            uint32_t a_h[2][4], b_h[4][4];
            const uint32_t kb = ks * 32;
            #pragma unroll
            for (int ma = 0; ma < 2; ++ma)
                LDSM4(a_h[ma], sb + a_off + ma * 16 * SA + kb);
            #pragma unroll
            for (int g = 0; g < 4; ++g)
                LDSM4(b_h[g], bcur + b_off + g * 16 * SA + kb);
            #pragma unroll
            for (int ma = 0; ma < 2; ++ma)
                #pragma unroll
                for (int g = 0; g < 4; ++g) {
                    MMA16816(acc[ma][2 * g],     a_h[ma], b_h[g][0], b_h[g][1]);
                    MMA16816(acc[ma][2 * g + 1], a_h[ma], b_h[g][2], b_h[g][3]);
                }
        }

        const int tb = c0 + t * 128;
        #pragma unroll
        for (int na = 0; na < 8; ++na) {
            const int cA = wn * 64 + na * 8 + (lane & 3) * 2;
            const float2 lp = *(const float2*)(flg + tb + cA);
            const uint64_t fl2 = pk2(lp.x, lp.y);
            #pragma unroll
            for (int ma = 0; ma < 2; ++ma) {
                float* c = acc[ma][na];
                uint64_t ea = fexp5_2(pk2(c[0], c[1]));
                uint64_t eb = fexp5_2(pk2(c[2], c[3]));
                if (CLS) {
                    dn2[ma][0] = fma2(ea, fl2, dn2[ma][0]);
                    dn2[ma][1] = fma2(eb, fl2, dn2[ma][1]);
                } else {
                    dn2[ma][0] = add2(dn2[ma][0], ea);
                    dn2[ma][1] = add2(dn2[ma][1], eb);
                    x12[ma][0] = fma2(ea, fl2, x12[ma][0]);
                    x12[ma][1] = fma2(eb, fl2, x12[ma][1]);
                }
                c[0] = 0.0f; c[1] = 0.0f; c[2] = 0.0f; c[3] = 0.0f;
            }
        }

        if (t + 1 < TCOLS) {
            asm volatile("cp.async.wait_group 0;" ::: "memory");
        }
        __syncthreads();
    }

    float dn[2][2], x1[2][2];
    #pragma unroll
    for (int ma = 0; ma < 2; ++ma)
        #pragma unroll
        for (int rp = 0; rp < 2; ++rp) {
            float a, b;
            upk2(dn2[ma][rp], a, b); dn[ma][rp] = a + b;
            upk2(x12[ma][rp], a, b); x1[ma][rp] = a + b;
            #pragma unroll
            for (int o = 1; o <= 2; o <<= 1) {
                dn[ma][rp] += __shfl_xor_sync(0xffffffffu, dn[ma][rp], o);
                if (!CLS) x1[ma][rp] += __shfl_xor_sync(0xffffffffu, x1[ma][rp], o);
            }
        }

    float* red = (float*)smem;
    __syncthreads();
    if (wn == 1 && (lane & 3) == 0) {
        #pragma unroll
        for (int ma = 0; ma < 2; ++ma)
            #pragma unroll
            for (int rp = 0; rp < 2; ++rp) {
                int rl = wm * 32 + ma * 16 + rp * 8 + (lane >> 2);
                red[rl * 2 + 0] = dn[ma][rp];
                red[rl * 2 + 1] = x1[ma][rp];
            }
    }
    __syncthreads();
    if (wn == 0 && (lane & 3) == 0) {
        const int s = by;
        #pragma unroll
        for (int ma = 0; ma < 2; ++ma)
            #pragma unroll
            for (int rp = 0; rp < 2; ++rp) {
                int rl = wm * 32 + ma * 16 + rp * 8 + (lane >> 2);
                float a = dn[ma][rp] + red[rl * 2 + 0];
                int g = bm + rl;
                if (CLS) {
                    g_pcl[(size_t)s * NR + g] = a;
                } else {
                    float b = x1[ma][rp] + red[rl * 2 + 1];
                    g_pfg[((size_t)s * NR + g) * 2 + 0] = a;
                    g_pfg[((size_t)s * NR + g) * 2 + 1] = b;
                }
            }
    }
}

__global__ __launch_bounds__(256, 2) void sim_all_kernel() {
    extern __shared__ char smem[];
    if (blockIdx.x < 64 * NSPL_CLS) {
        sim_body<CLDIM, true, NSPL_CLS>(blockIdx.x >> 2, blockIdx.x & 3, smem);
    } else {
        const int b = blockIdx.x - 64 * NSPL_CLS;
        sim_body<FGDIM, false, NSPL_FG>(b >> 2, b & 3, smem);
    }
}

// ---------------- final deterministic reduction ----------------
__global__ void finalize_kernel(float* __restrict__ out) {
    __shared__ int hist[22];
    __shared__ float red[256][4];
    int tid = threadIdx.x;
    if (tid < 22) hist[tid] = 0;
    __syncthreads();
    for (int i = tid; i < NR; i += 256) atomicAdd(&hist[g_lbl[i] + 1], 1);
    __syncthreads();
    int nnon = NR - hist[0];
    int nfgset = nnon - hist[1];
    float nfg = 0.0f, dfg = 0.0f, ncl = 0.0f, dcl = 0.0f;
    for (int i = tid; i < NR; i += 256) {
        int l = g_lbl[i];
        if (l > 0) {
            float w = g_wgt[i];
            float dnv = 0.0f, nm = 0.0f;
            #pragma unroll
            for (int s = 0; s < NSPL_FG; ++s) {
                dnv += g_pfg[((size_t)s * NR + i) * 2 + 0];
                nm  += g_pfg[((size_t)s * NR + i) * 2 + 1];
            }
            float ef = g_eiif[i];
            dnv -= ef; nm -= ef;
            if (nfgset - 1 > 0) {
                float li = -logf((nm + 1e-8f) / (dnv + 1e-8f));
                nfg += li * w; dfg += w;
            }
            float dc = 0.0f;
            #pragma unroll
            for (int s = 0; s < NSPL_CLS; ++s)
                dc += g_pcl[(size_t)s * NR + i];
            dc -= g_eiic[i];
            float np = (float)(hist[l + 1] - 1);
            if (np > 0.5f && (nnon - 1) > 0) {
                float li = -(g_sp[i] - np * logf(dc)) / np;
                ncl += li * w; dcl += w;
            }
        }
    }
    red[tid][0] = nfg; red[tid][1] = dfg; red[tid][2] = ncl; red[tid][3] = dcl;
    __syncthreads();
    for (int s = 128; s > 0; s >>= 1) {
        if (tid < s) {
            red[tid][0] += red[tid + s][0]; red[tid][1] += red[tid + s][1];
            red[tid][2] += red[tid + s][2]; red[tid][3] += red[tid + s][3];
        }
        __syncthreads();
    }
    if (tid == 0) {
        out[0] = red[0][0] / (red[0][1] + 1e-8f);
        out[1] = red[0][2] / (red[0][3] + 1e-12f);
    }
}

// ---------------- launch ----------------
extern "C" void kernel_launch(void* const* d_in, const int* in_sizes, int n_in,
                              void* d_out, int out_size) {
    const float* roi = (const float*)d_in[0];
    const int*   lab = (const int*)d_in[1];
    const float* iou = (const float*)d_in[2];
    const float* w1f = (const float*)d_in[3];
    const float* b1f = (const float*)d_in[4];
    const float* w2f = (const float*)d_in[5];
    const float* b2f = (const float*)d_in[6];
    const float* w1c = (const float*)d_in[7];
    const float* b1c = (const float*)d_in[8];
    const float* w2c = (const float*)d_in[9];
    const float* b2c = (const float*)d_in[10];

    constexpr int SM_G128 = 2 * (2 * 128 * 144 + 2 * 128 * 144);   // 147456
    constexpr int SMEM_SIM = 3 * 128 * (CLDIM * 2 + 16);           // 104448
    cudaFuncSetAttribute(mma_gemm1,      cudaFuncAttributeMaxDynamicSharedMemorySize, SM_G128);
    cudaFuncSetAttribute(mma_gemm2_all,  cudaFuncAttributeMaxDynamicSharedMemorySize, SM_G128);
    cudaFuncSetAttribute(sim_all_kernel, cudaFuncAttributeMaxDynamicSharedMemorySize, SMEM_SIM);

    prep_conv_kernel<<<CONV_BLKS + NR / 256, 256>>>(roi, w1f, w1c, w2f, w2c, lab, iou);

    mma_gemm1<<<dim3(HD / 128, NR / 128, 2), 256, SM_G128>>>(b1f, b1c);

    mma_gemm2_all<<<128, 256, SM_G128>>>(b2f, b2c);

    class_sum1_kernel<<<CSBLK, CLDIM>>>();
    class_sum2_kernel<<<20, CLDIM>>>();
    row_sp_kernel<<<NR / 8, 256>>>();

    sim_all_kernel<<<64 * NSPL_CLS + 64 * NSPL_FG, 256, SMEM_SIM>>>();

    finalize_kernel<<<1, 256>>>((float*)d_out);
}

// round 14
// speedup vs baseline: 1.0219x; 1.0219x over previous
#include <cuda_runtime.h>
#include <cuda_bf16.h>
#include <math.h>
#include <stdint.h>

#define NR 8192
#define CD 1024
#define HD 256
#define FGDIM 64
#define CLDIM 128
#define NSPL_FG 4
#define NSPL_CLS 4
#define CSBLK 256   // class-sum partial blocks (32 rows each)

// ---------------- device scratch (no allocs allowed) ----------------
__device__ __nv_bfloat16 g_Xh[NR * CD];
__device__ __nv_bfloat16 g_Xl[NR * CD];
__device__ __nv_bfloat16 g_W1fh[HD * CD];
__device__ __nv_bfloat16 g_W1fl[HD * CD];
__device__ __nv_bfloat16 g_W1ch[HD * CD];
__device__ __nv_bfloat16 g_W1cl[HD * CD];
__device__ __nv_bfloat16 g_W2fh[FGDIM * HD];
__device__ __nv_bfloat16 g_W2fl[FGDIM * HD];
__device__ __nv_bfloat16 g_W2ch[CLDIM * HD];
__device__ __nv_bfloat16 g_W2cl[CLDIM * HD];
__device__ __nv_bfloat16 g_Hfh[NR * HD];
__device__ __nv_bfloat16 g_Hfl[NR * HD];
__device__ __nv_bfloat16 g_Hch[NR * HD];
__device__ __nv_bfloat16 g_Hcl[NR * HD];
__device__ float g_Zc[NR * CLDIM];            // CLS fp32 (original row order)
__device__ __nv_bfloat16 g_Zfh[NR * FGDIM];
__device__ __nv_bfloat16 g_Zch[NR * CLDIM];
__device__ float g_pfg[NSPL_FG * NR * 2];     // per split, per row: denom, numer
__device__ float g_pcl[NSPL_CLS * NR];        // per split, per row: denom
__device__ float g_Sp[20 * CSBLK * CLDIM];    // per-class per-block partial sums
__device__ float g_S[20 * CLDIM];
__device__ float g_sp[NR];                    // per-row sum_pos (CLS)
__device__ float g_eiif[NR];                  // per-row self exp (FG, hi*hi)
__device__ float g_eiic[NR];                  // per-row self exp (CLS, hi*hi)
__device__ float g_ssc[NR];                   // per-row ||z||^2 (CLS)
__device__ int   g_lbl[NR];
__device__ float g_fgf[NR];
__device__ float g_vld[NR];
__device__ float g_wgt[NR];

// ---------------- helpers ----------------
__device__ __forceinline__ uint32_t smem_u32(const void* p) {
    uint32_t a;
    asm("{ .reg .u64 t; cvta.to.shared.u64 t, %1; cvt.u32.u64 %0, t; }" : "=r"(a) : "l"(p));
    return a;
}

#define LDSM4(r, addr) \
    asm volatile("ldmatrix.sync.aligned.m8n8.x4.shared.b16 {%0,%1,%2,%3}, [%4];" \
        : "=r"((r)[0]), "=r"((r)[1]), "=r"((r)[2]), "=r"((r)[3]) : "r"(addr))

#define MMA16816(d, a, b0, b1) \
    asm volatile("mma.sync.aligned.m16n8k16.row.col.f32.bf16.bf16.f32 " \
        "{%0,%1,%2,%3},{%4,%5,%6,%7},{%8,%9},{%0,%1,%2,%3};" \
        : "+f"((d)[0]), "+f"((d)[1]), "+f"((d)[2]), "+f"((d)[3]) \
        : "r"((a)[0]), "r"((a)[1]), "r"((a)[2]), "r"((a)[3]), "r"(b0), "r"(b1))

// ---------------- packed f32x2 ops ----------------
__device__ __forceinline__ uint64_t pk2(float a, float b) {
    uint64_t r; asm("mov.b64 %0, {%1, %2};" : "=l"(r) : "f"(a), "f"(b)); return r;
}
__device__ __forceinline__ void upk2(uint64_t v, float& a, float& b) {
    asm("mov.b64 {%0, %1}, %2;" : "=f"(a), "=f"(b) : "l"(v));
}
__device__ __forceinline__ uint64_t fma2(uint64_t a, uint64_t b, uint64_t c) {
    uint64_t d; asm("fma.rn.f32x2 %0, %1, %2, %3;" : "=l"(d) : "l"(a), "l"(b), "l"(c)); return d;
}
__device__ __forceinline__ uint64_t add2(uint64_t a, uint64_t b) {
    uint64_t d; asm("add.rn.f32x2 %0, %1, %2;" : "=l"(d) : "l"(a), "l"(b)); return d;
}
__device__ __forceinline__ uint64_t mul2(uint64_t a, uint64_t b) {
    uint64_t d; asm("mul.rn.f32x2 %0, %1, %2;" : "=l"(d) : "l"(a), "l"(b)); return d;
}

// packed exp(5x): range reduce + cubic 2^f on [-0.5, 0.5]
__device__ __forceinline__ uint64_t fexp5_2(uint64_t x2) {
    const float KE = 7.2134752044448169f;   // 5 * log2(e)
    const float SH = 12582912.0f;           // 1.5 * 2^23
    const uint64_t KE2 = pk2(KE, KE);
    const uint64_t SH2 = pk2(SH, SH);
    const uint64_t N12 = pk2(-1.0f, -1.0f);
    uint64_t z2 = fma2(x2, KE2, SH2);
    float zl, zh; upk2(z2, zl, zh);
    int e0 = (__float_as_int(zl) - 0x4B3FFF81) << 23;
    int e1 = (__float_as_int(zh) - 0x4B3FFF81) << 23;
    uint64_t nr2 = fma2(z2, N12, SH2);
    uint64_t f2 = fma2(x2, KE2, nr2);
    uint64_t p = pk2(0.0559174f, 0.0559174f);
    p = fma2(p, f2, pk2(0.2426311f, 0.2426311f));
    p = fma2(p, f2, pk2(0.6930790f, 0.6930790f));
    p = fma2(p, f2, pk2(0.9999247f, 0.9999247f));
    return mul2(p, pk2(__int_as_float(e0), __int_as_float(e1)));
}

// scalar exp(5x), degree-4
__device__ __forceinline__ float fexp5(float x) {
    const float KE = 7.2134752044448169f;
    const float SH = 12582912.0f;
    float z = fmaf(x, KE, SH);
    int   ei = __float_as_int(z);
    float r = z - SH;
    float f = fmaf(x, KE, -r);
    float p = 9.6181291076284771e-3f;
    p = fmaf(p, f, 5.5504108664821580e-2f);
    p = fmaf(p, f, 2.4022650695910071e-1f);
    p = fmaf(p, f, 6.9314718055994531e-1f);
    p = fmaf(p, f, 1.0f);
    return p * __int_as_float((ei - 0x4B400000 + 127) << 23);
}

// ---------------- merged prep + hi/lo conversions (one launch) ----------------
#define SEG_X   2097152
#define SEG_W1F 2162688
#define SEG_W1C 2228224
#define SEG_W2F 2232320
#define SEG_W2C 2240512
#define CONV_BLKS 8752

__global__ void prep_conv_kernel(const float* __restrict__ roi,
                                 const float* __restrict__ w1f, const float* __restrict__ w1c,
                                 const float* __restrict__ w2f, const float* __restrict__ w2c,
                                 const int* __restrict__ lraw, const float* __restrict__ ious) {
    if (blockIdx.x >= CONV_BLKS) {
        int i = (blockIdx.x - CONV_BLKS) * 256 + threadIdx.x;
        bool is64 = true;
        #pragma unroll 1
        for (int p = 0; p < 32; ++p) {
            int lo = lraw[2 * p], hi = lraw[2 * p + 1];
            bool ok = (hi == 0 && lo >= 0) || (hi == -1 && lo < 0);
            if (!ok) { is64 = false; break; }
        }
        int l = is64 ? (int)(((const long long*)lraw)[i]) : lraw[i];
        g_lbl[i] = l;
        g_fgf[i] = (l > 0) ? 1.0f : 0.0f;
        g_vld[i] = (l != -1) ? 1.0f : 0.0f;
        float u = ious[i];
        g_wgt[i] = (u > 0.5f) ? u : 0.0f;
        return;
    }
    int i = blockIdx.x * 256 + threadIdx.x;
    const float* s; __nv_bfloat16 *h, *l; int base;
    if (i < SEG_X)        { s = roi; h = g_Xh;   l = g_Xl;   base = 0; }
    else if (i < SEG_W1F) { s = w1f; h = g_W1fh; l = g_W1fl; base = SEG_X; }
    else if (i < SEG_W1C) { s = w1c; h = g_W1ch; l = g_W1cl; base = SEG_W1F; }
    else if (i < SEG_W2F) { s = w2f; h = g_W2fh; l = g_W2fl; base = SEG_W1C; }
    else                  { s = w2c; h = g_W2ch; l = g_W2cl; base = SEG_W2F; }
    int j = i - base;
    float4 v = ((const float4*)s)[j];
    __nv_bfloat162 h0, h1, l0, l1;
    h0.x = __float2bfloat16(v.x); h0.y = __float2bfloat16(v.y);
    h1.x = __float2bfloat16(v.z); h1.y = __float2bfloat16(v.w);
    l0.x = __float2bfloat16(v.x - __bfloat162float(h0.x));
    l0.y = __float2bfloat16(v.y - __bfloat162float(h0.y));
    l1.x = __float2bfloat16(v.z - __bfloat162float(h1.x));
    l1.y = __float2bfloat16(v.w - __bfloat162float(h1.y));
    ((__nv_bfloat162*)h)[j * 2] = h0; ((__nv_bfloat162*)h)[j * 2 + 1] = h1;
    ((__nv_bfloat162*)l)[j * 2] = l0; ((__nv_bfloat162*)l)[j * 2 + 1] = l1;
}

// ---------------- cp.async bf16 tile loader (BK=64, padded stride 144B) ----------------
__device__ __forceinline__ void ld_tile64(uint32_t dst, const __nv_bfloat16* __restrict__ src,
                                          int rows, int K, int tid) {
    #pragma unroll 4
    for (int i = tid; i < rows * 8; i += 256) {
        int r = i >> 3, c = i & 7;
        asm volatile("cp.async.cg.shared.global [%0], [%1], 16;"
                     :: "r"(dst + r * 144 + c * 16), "l"(src + (size_t)r * K + c * 8) : "memory");
    }
}

// ---------------- layer-1 MMA GEMM (3-chain, relu + hi/lo split out) ----------------
__global__ __launch_bounds__(256) void mma_gemm1(
    const float* __restrict__ bias0, const float* __restrict__ bias1) {
    constexpr int BN = 128, SA = 144;
    constexpr int ATS = 128 * SA;
    constexpr int BTS = BN * SA;
    constexpr int STG = 2 * ATS + 2 * BTS;
    constexpr int NG = BN / 32, NF = 2 * NG;
    constexpr int N = HD, K = CD;

    extern __shared__ char smem[];
    uint32_t sb = smem_u32(smem);
    const int tid = threadIdx.x, wid = tid >> 5, lane = tid & 31;
    const int wm = wid & 3, wn = wid >> 2;
    const int z = blockIdx.z;
    const int bm = blockIdx.y * 128, bn = blockIdx.x * BN;

    const __nv_bfloat16* Ah = g_Xh;
    const __nv_bfloat16* Al = g_Xl;
    const __nv_bfloat16* Wh = z ? g_W1ch : g_W1fh;
    const __nv_bfloat16* Wl = z ? g_W1cl : g_W1fl;
    const float* bias = z ? bias1 : bias0;
    __nv_bfloat16* oh = z ? g_Hch : g_Hfh;
    __nv_bfloat16* ol = z ? g_Hcl : g_Hfl;

    const int KC = K >> 6;

    ld_tile64(sb, Ah + (size_t)bm * K, 128, K, tid);
    ld_tile64(sb + ATS, Al + (size_t)bm * K, 128, K, tid);
    ld_tile64(sb + 2 * ATS, Wh + (size_t)bn * K, BN, K, tid);
    ld_tile64(sb + 2 * ATS + BTS, Wl + (size_t)bn * K, BN, K, tid);
    asm volatile("cp.async.commit_group;" ::: "memory");

    float acc[2][NF][4];
    #pragma unroll
    for (int ma = 0; ma < 2; ++ma)
        #pragma unroll
        for (int nf = 0; nf < NF; ++nf)
            #pragma unroll
            for (int e = 0; e < 4; ++e) acc[ma][nf][e] = 0.0f;

    const uint32_t a_off = (uint32_t)((wm * 32 + (lane & 15)) * SA + (lane >> 4) * 16);
    const uint32_t b_off = (uint32_t)((wn * (BN / 2) + ((lane >> 4) << 3) + (lane & 7)) * SA + ((lane >> 3) & 1) * 16);

    for (int kc = 0; kc < KC; ++kc) {
        const uint32_t cur = sb + (kc & 1) * STG;
        if (kc + 1 < KC) {
            const uint32_t nxt = sb + ((kc + 1) & 1) * STG;
            const int ko = (kc + 1) * 64;
            ld_tile64(nxt, Ah + (size_t)bm * K + ko, 128, K, tid);
            ld_tile64(nxt + ATS, Al + (size_t)bm * K + ko, 128, K, tid);
            ld_tile64(nxt + 2 * ATS, Wh + (size_t)bn * K + ko, BN, K, tid);
            ld_tile64(nxt + 2 * ATS + BTS, Wl + (size_t)bn * K + ko, BN, K, tid);
            asm volatile("cp.async.commit_group;" ::: "memory");
            asm volatile("cp.async.wait_group 1;" ::: "memory");
        } else {
            asm volatile("cp.async.wait_group 0;" ::: "memory");
        }
        __syncthreads();

        #pragma unroll
        for (int ks = 0; ks < 4; ++ks) {
            const uint32_t kb = ks * 32;
            uint32_t a_h[2][4], a_l[2][4], b_h[NG][4], b_l[NG][4];
            #pragma unroll
            for (int ma = 0; ma < 2; ++ma) {
                LDSM4(a_h[ma], cur + a_off + ma * 16 * SA + kb);
                LDSM4(a_l[ma], cur + ATS + a_off + ma * 16 * SA + kb);
            }
            #pragma unroll
            for (int g = 0; g < NG; ++g) {
                LDSM4(b_h[g], cur + 2 * ATS + b_off + g * 16 * SA + kb);
                LDSM4(b_l[g], cur + 2 * ATS + BTS + b_off + g * 16 * SA + kb);
            }
            #pragma unroll
            for (int ma = 0; ma < 2; ++ma)
                #pragma unroll
                for (int g = 0; g < NG; ++g) {
                    MMA16816(acc[ma][2 * g],     a_h[ma], b_h[g][0], b_h[g][1]);
                    MMA16816(acc[ma][2 * g + 1], a_h[ma], b_h[g][2], b_h[g][3]);
                    MMA16816(acc[ma][2 * g],     a_h[ma], b_l[g][0], b_l[g][1]);
                    MMA16816(acc[ma][2 * g + 1], a_h[ma], b_l[g][2], b_l[g][3]);
                    MMA16816(acc[ma][2 * g],     a_l[ma], b_h[g][0], b_h[g][1]);
                    MMA16816(acc[ma][2 * g + 1], a_l[ma], b_h[g][2], b_h[g][3]);
                }
        }
        __syncthreads();
    }

    #pragma unroll
    for (int ma = 0; ma < 2; ++ma)
        #pragma unroll
        for (int nf = 0; nf < NF; ++nf)
            #pragma unroll
            for (int rp = 0; rp < 2; ++rp) {
                const int r = bm + wm * 32 + ma * 16 + rp * 8 + (lane >> 2);
                const int c = bn + wn * (BN / 2) + nf * 8 + (lane & 3) * 2;
                float2 bb = *(const float2*)(bias + c);
                float v0 = fmaxf(acc[ma][nf][rp * 2 + 0] + bb.x, 0.0f);
                float v1 = fmaxf(acc[ma][nf][rp * 2 + 1] + bb.y, 0.0f);
                __nv_bfloat162 hv, lv;
                hv.x = __float2bfloat16(v0); hv.y = __float2bfloat16(v1);
                lv.x = __float2bfloat16(v0 - __bfloat162float(hv.x));
                lv.y = __float2bfloat16(v1 - __bfloat162float(hv.y));
                *(__nv_bfloat162*)(oh + (size_t)r * N + c) = hv;
                *(__nv_bfloat162*)(ol + (size_t)r * N + c) = lv;
            }
}

// ---------------- layer-2 body: GEMM + fused normalize + hi-split + eii/ss ----------------
template<int BN>
__device__ __forceinline__ void gemm2_body(
    const __nv_bfloat16* __restrict__ Ah, const __nv_bfloat16* __restrict__ Al,
    const __nv_bfloat16* __restrict__ Wh, const __nv_bfloat16* __restrict__ Wl,
    const float* __restrict__ bias,
    float* __restrict__ Zout, __nv_bfloat16* __restrict__ Oh,
    float* __restrict__ eii, float* __restrict__ ssout,
    int bm, char* smem) {
    constexpr int SA = 144;
    constexpr int ATS = 128 * SA;
    constexpr int BTS = BN * SA;
    constexpr int STG = 2 * ATS + 2 * BTS;
    constexpr int NG = BN / 32, NF = 2 * NG;
    constexpr int K = HD;
    constexpr int ZS = BN + 4;

    uint32_t sb = smem_u32(smem);
    float* zbuf = (float*)smem;
    const int tid = threadIdx.x, wid = tid >> 5, lane = tid & 31;
    const int wm = wid & 3, wn = wid >> 2;

    const int KC = K >> 6;

    ld_tile64(sb, Ah + (size_t)bm * K, 128, K, tid);
    ld_tile64(sb + ATS, Al + (size_t)bm * K, 128, K, tid);
    ld_tile64(sb + 2 * ATS, Wh, BN, K, tid);
    ld_tile64(sb + 2 * ATS + BTS, Wl, BN, K, tid);
    asm volatile("cp.async.commit_group;" ::: "memory");

    float acc[2][NF][4];
    #pragma unroll
    for (int ma = 0; ma < 2; ++ma)
        #pragma unroll
        for (int nf = 0; nf < NF; ++nf)
            #pragma unroll
            for (int e = 0; e < 4; ++e) acc[ma][nf][e] = 0.0f;

    const uint32_t a_off = (uint32_t)((wm * 32 + (lane & 15)) * SA + (lane >> 4) * 16);
    const uint32_t b_off = (uint32_t)((wn * (BN / 2) + ((lane >> 4) << 3) + (lane & 7)) * SA + ((lane >> 3) & 1) * 16);

    for (int kc = 0; kc < KC; ++kc) {
        const uint32_t cur = sb + (kc & 1) * STG;
        if (kc + 1 < KC) {
            const uint32_t nxt = sb + ((kc + 1) & 1) * STG;
            const int ko = (kc + 1) * 64;
            ld_tile64(nxt, Ah + (size_t)bm * K + ko, 128, K, tid);
            ld_tile64(nxt + ATS, Al + (size_t)bm * K + ko, 128, K, tid);
            ld_tile64(nxt + 2 * ATS, Wh + ko, BN, K, tid);
            ld_tile64(nxt + 2 * ATS + BTS, Wl + ko, BN, K, tid);
            asm volatile("cp.async.commit_group;" ::: "memory");
            asm volatile("cp.async.wait_group 1;" ::: "memory");
        } else {
            asm volatile("cp.async.wait_group 0;" ::: "memory");
        }
        __syncthreads();

        #pragma unroll
        for (int ks = 0; ks < 4; ++ks) {
            const uint32_t kb = ks * 32;
            uint32_t a_h[2][4], a_l[2][4], b_h[NG][4], b_l[NG][4];
            #pragma unroll
            for (int ma = 0; ma < 2; ++ma) {
                LDSM4(a_h[ma], cur + a_off + ma * 16 * SA + kb);
                LDSM4(a_l[ma], cur + ATS + a_off + ma * 16 * SA + kb);
            }
            #pragma unroll
            for (int g = 0; g < NG; ++g) {
                LDSM4(b_h[g], cur + 2 * ATS + b_off + g * 16 * SA + kb);
                LDSM4(b_l[g], cur + 2 * ATS + BTS + b_off + g * 16 * SA + kb);
            }
            #pragma unroll
            for (int ma = 0; ma < 2; ++ma)
                #pragma unroll
                for (int g = 0; g < NG; ++g) {
                    MMA16816(acc[ma][2 * g],     a_h[ma], b_h[g][0], b_h[g][1]);
                    MMA16816(acc[ma][2 * g + 1], a_h[ma], b_h[g][2], b_h[g][3]);
                    MMA16816(acc[ma][2 * g],     a_h[ma], b_l[g][0], b_l[g][1]);
                    MMA16816(acc[ma][2 * g + 1], a_h[ma], b_l[g][2], b_l[g][3]);
                    MMA16816(acc[ma][2 * g],     a_l[ma], b_h[g][0], b_h[g][1]);
                    MMA16816(acc[ma][2 * g + 1], a_l[ma], b_h[g][2], b_h[g][3]);
                }
        }
        __syncthreads();
    }

    #pragma unroll
    for (int ma = 0; ma < 2; ++ma)
        #pragma unroll
        for (int nf = 0; nf < NF; ++nf)
            #pragma unroll
            for (int rp = 0; rp < 2; ++rp) {
                const int r = wm * 32 + ma * 16 + rp * 8 + (lane >> 2);
                const int c = wn * (BN / 2) + nf * 8 + (lane & 3) * 2;
                float2 bb = *(const float2*)(bias + c);
                zbuf[r * ZS + c] = acc[ma][nf][rp * 2 + 0] + bb.x;
                zbuf[r * ZS + c + 1] = acc[ma][nf][rp * 2 + 1] + bb.y;
            }
    __syncthreads();

    constexpr int CE = BN / 32;
    for (int rr = 0; rr < 16; ++rr) {
        const int r = wid * 16 + rr;
        const int grow = bm + r;
        float v[CE];
        float ss = 0.0f;
        #pragma unroll
        for (int q = 0; q < CE; ++q) { v[q] = zbuf[r * ZS + lane + q * 32]; ss += v[q] * v[q]; }
        #pragma unroll
        for (int o = 16; o; o >>= 1) ss += __shfl_xor_sync(0xffffffffu, ss, o);
        const float inv = 1.0f / fmaxf(sqrtf(ss), 1e-8f);
        float hh = 0.0f;
        #pragma unroll
        for (int q = 0; q < CE; ++q) {
            float zv = v[q] * inv;
            if (Zout) Zout[(size_t)grow * BN + lane + q * 32] = zv;
            __nv_bfloat16 h = __float2bfloat16(zv);
            Oh[(size_t)grow * BN + lane + q * 32] = h;
            float hf = __bfloat162float(h);
            hh = fmaf(hf, hf, hh);
        }
        #pragma unroll
        for (int o = 16; o; o >>= 1) hh += __shfl_xor_sync(0xffffffffu, hh, o);
        if (lane == 0) {
            eii[grow] = fexp5(hh);
            if (ssout) ssout[grow] = ss * inv * inv;
        }
    }
}

__global__ __launch_bounds__(256) void mma_gemm2_all(
    const float* __restrict__ b2f, const float* __restrict__ b2c) {
    extern __shared__ char smem[];
    if (blockIdx.x < 64)
        gemm2_body<FGDIM>(g_Hfh, g_Hfl, g_W2fh, g_W2fl, b2f,
                          nullptr, g_Zfh, g_eiif, nullptr,
                          blockIdx.x * 128, smem);
    else
        gemm2_body<CLDIM>(g_Hch, g_Hcl, g_W2ch, g_W2cl, b2c,
                          g_Zc, g_Zch, g_eiic, g_ssc,
                          (blockIdx.x - 64) * 128, smem);
}

// ---------------- per-class z sums: batch-4 prefetch row-pass ----------------
__global__ void class_sum1_kernel() {     // grid CSBLK (256), block CLDIM (128), 32 rows each
    __shared__ float sh[20][CLDIM];
    const int d = threadIdx.x;
    #pragma unroll
    for (int c = 0; c < 20; ++c) sh[c][d] = 0.0f;
    const int i0 = blockIdx.x * (NR / CSBLK);
    constexpr int NB = (NR / CSBLK) / 4;   // 8 batches of 4 rows
    int   lc[4];
    float vc[4];
    #pragma unroll
    for (int k = 0; k < 4; ++k) {
        lc[k] = g_lbl[i0 + k];
        vc[k] = g_Zc[(size_t)(i0 + k) * CLDIM + d];
    }
    #pragma unroll 1
    for (int b = 0; b < NB; ++b) {
        int   ln[4];
        float vn[4];
        if (b + 1 < NB) {
            const int ib = i0 + (b + 1) * 4;
            #pragma unroll
            for (int k = 0; k < 4; ++k) {
                ln[k] = g_lbl[ib + k];
                vn[k] = g_Zc[(size_t)(ib + k) * CLDIM + d];
            }
        }
        #pragma unroll
        for (int k = 0; k < 4; ++k)
            if (lc[k] > 0) sh[lc[k] - 1][d] += vc[k];
        #pragma unroll
        for (int k = 0; k < 4; ++k) { lc[k] = ln[k]; vc[k] = vn[k]; }
    }
    #pragma unroll
    for (int c = 0; c < 20; ++c)
        g_Sp[((size_t)c * CSBLK + blockIdx.x) * CLDIM + d] = sh[c][d];
}
__global__ void class_sum2_kernel() {     // grid 20, block CLDIM
    float s = 0.0f;
    #pragma unroll 8
    for (int g = 0; g < CSBLK; ++g)
        s += g_Sp[((size_t)blockIdx.x * CSBLK + g) * CLDIM + threadIdx.x];
    g_S[blockIdx.x * CLDIM + threadIdx.x] = s;
}

// ---------------- per-row sum_pos for CLS (warp per row) ----------------
__global__ void row_sp_kernel() {
    int row = blockIdx.x * 8 + (threadIdx.x >> 5);
    int lane = threadIdx.x & 31;
    int l = g_lbl[row];
    const float* S = g_S + (l > 0 ? (l - 1) : 0) * CLDIM;
    float sd = 0.0f;
    #pragma unroll
    for (int c = lane; c < CLDIM; c += 32)
        sd += g_Zc[(size_t)row * CLDIM + c] * S[c];
    #pragma unroll
    for (int o = 16; o; o >>= 1) sd += __shfl_xor_sync(0xffffffffu, sd, o);
    if (lane == 0) g_sp[row] = 5.0f * (sd - g_ssc[row]);
}

// ---------------- cp.async tile loader for sim (full K resident) ----------------
template<int KD>
__device__ __forceinline__ void load_tile(uint32_t dst, const __nv_bfloat16* __restrict__ src, int tid) {
    constexpr int CPR = KD / 8;
    constexpr int SA = KD * 2 + 16;
    #pragma unroll
    for (int i = tid; i < 128 * CPR; i += 256) {
        int r = i / CPR, c = i % CPR;
        asm volatile("cp.async.cg.shared.global [%0], [%1], 16;"
                     :: "r"(dst + r * SA + c * 16), "l"(src + (size_t)r * KD + c * 8) : "memory");
    }
}

// ---------------- sim body (1-chain hi*hi, flag-load packed epilogue) ----------------
template<int KD, bool CLS, int NSPLT>
__device__ __forceinline__ void sim_body(int bx, int by, char* smem) {
    constexpr int SA = KD * 2 + 16;
    constexpr int TSZ = 128 * SA;
    constexpr int SLAB = NR / NSPLT;
    constexpr int TCOLS = SLAB / 128;
    constexpr int KSTEPS = KD / 16;
    constexpr int B_OFF = TSZ;

    uint32_t sb = smem_u32(smem);
    const int tid = threadIdx.x, wid = tid >> 5, lane = tid & 31;
    const int wm = wid & 3, wn = wid >> 2;
    const int bm = bx * 128;
    const int c0 = by * SLAB;
    const __nv_bfloat16* Zh = CLS ? g_Zch : g_Zfh;
    const float* flg = CLS ? g_vld : g_fgf;

    load_tile<KD>(sb, Zh + (size_t)bm * KD, tid);
    load_tile<KD>(sb + B_OFF, Zh + (size_t)c0 * KD, tid);
    asm volatile("cp.async.commit_group;" ::: "memory");

    uint64_t dn2[2][2] = {{0ull, 0ull}, {0ull, 0ull}};
    uint64_t x12[2][2] = {{0ull, 0ull}, {0ull, 0ull}};

    const uint32_t a_off = (uint32_t)((wm * 32 + (lane & 15)) * SA + (lane >> 4) * 16);
    const uint32_t b_off = (uint32_t)((wn * 64 + ((lane >> 4) << 3) + (lane & 7)) * SA + ((lane >> 3) & 1) * 16);

    float acc[2][8][4];
    #pragma unroll
    for (int ma = 0; ma < 2; ++ma)
        #pragma unroll
        for (int na = 0; na < 8; ++na)
            #pragma unroll
            for (int e = 0; e < 4; ++e) acc[ma][na][e] = 0.0f;

    asm volatile("cp.async.wait_group 0;" ::: "memory");
    __syncthreads();

    for (int t = 0; t < TCOLS; ++t) {
        const uint32_t bcur = sb + B_OFF + (t & 1) * TSZ;
        if (t + 1 < TCOLS) {
            load_tile<KD>(sb + B_OFF + ((t + 1) & 1) * TSZ,
                          Zh + (size_t)(c0 + (t + 1) * 128) * KD, tid);
            asm volatile("cp.async.commit_group;" ::: "memory");
        }

        #pragma unroll
        for (int ks = 0; ks < KSTEPS; ++ks) {
            uint32_t a_h[2][4], b_h[4][4];
            const uint32_t kb = ks * 32;
            #pragma unroll
            for (int ma = 0; ma < 2; ++ma)
                LDSM4(a_h[ma], sb + a_off + ma * 16 * SA + kb);
            #pragma unroll
            for (int g = 0; g < 4; ++g)
                LDSM4(b_h[g], bcur + b_off + g * 16 * SA + kb);
            #pragma unroll
            for (int ma = 0; ma < 2; ++ma)
                #pragma unroll
                for (int g = 0; g < 4; ++g) {
                    MMA16816(acc[ma][2 * g],     a_h[ma], b_h[g][0], b_h[g][1]);
                    MMA16816(acc[ma][2 * g + 1], a_h[ma], b_h[g][2], b_h[g][3]);
                }
        }

        const int tb = c0 + t * 128;
        #pragma unroll
        for (int na = 0; na < 8; ++na) {
            const int cA = wn * 64 + na * 8 + (lane & 3) * 2;
            const float2 lp = *(const float2*)(flg + tb + cA);
            const uint64_t fl2 = pk2(lp.x, lp.y);
            #pragma unroll
            for (int ma = 0; ma < 2; ++ma) {
                float* c = acc[ma][na];
                uint64_t ea = fexp5_2(pk2(c[0], c[1]));
                uint64_t eb = fexp5_2(pk2(c[2], c[3]));
                if (CLS) {
                    dn2[ma][0] = fma2(ea, fl2, dn2[ma][0]);
                    dn2[ma][1] = fma2(eb, fl2, dn2[ma][1]);
                } else {
                    dn2[ma][0] = add2(dn2[ma][0], ea);
                    dn2[ma][1] = add2(dn2[ma][1], eb);
                    x12[ma][0] = fma2(ea, fl2, x12[ma][0]);
                    x12[ma][1] = fma2(eb, fl2, x12[ma][1]);
                }
                c[0] = 0.0f; c[1] = 0.0f; c[2] = 0.0f; c[3] = 0.0f;
            }
        }

        if (t + 1 < TCOLS) {
            asm volatile("cp.async.wait_group 0;" ::: "memory");
        }
        __syncthreads();
    }

    float dn[2][2], x1[2][2];
    #pragma unroll
    for (int ma = 0; ma < 2; ++ma)
        #pragma unroll
        for (int rp = 0; rp < 2; ++rp) {
            float a, b;
            upk2(dn2[ma][rp], a, b); dn[ma][rp] = a + b;
            upk2(x12[ma][rp], a, b); x1[ma][rp] = a + b;
            #pragma unroll
            for (int o = 1; o <= 2; o <<= 1) {
                dn[ma][rp] += __shfl_xor_sync(0xffffffffu, dn[ma][rp], o);
                if (!CLS) x1[ma][rp] += __shfl_xor_sync(0xffffffffu, x1[ma][rp], o);
            }
        }

    float* red = (float*)smem;
    __syncthreads();
    if (wn == 1 && (lane & 3) == 0) {
        #pragma unroll
        for (int ma = 0; ma < 2; ++ma)
            #pragma unroll
            for (int rp = 0; rp < 2; ++rp) {
                int rl = wm * 32 + ma * 16 + rp * 8 + (lane >> 2);
                red[rl * 2 + 0] = dn[ma][rp];
                red[rl * 2 + 1] = x1[ma][rp];
            }
    }
    __syncthreads();
    if (wn == 0 && (lane & 3) == 0) {
        const int s = by;
        #pragma unroll
        for (int ma = 0; ma < 2; ++ma)
            #pragma unroll
            for (int rp = 0; rp < 2; ++rp) {
                int rl = wm * 32 + ma * 16 + rp * 8 + (lane >> 2);
                float a = dn[ma][rp] + red[rl * 2 + 0];
                int g = bm + rl;
                if (CLS) {
                    g_pcl[(size_t)s * NR + g] = a;
                } else {
                    float b = x1[ma][rp] + red[rl * 2 + 1];
                    g_pfg[((size_t)s * NR + g) * 2 + 0] = a;
                    g_pfg[((size_t)s * NR + g) * 2 + 1] = b;
                }
            }
    }
}

__global__ __launch_bounds__(256, 2) void sim_all_kernel() {
    extern __shared__ char smem[];
    if (blockIdx.x < 64 * NSPL_CLS) {
        sim_body<CLDIM, true, NSPL_CLS>(blockIdx.x >> 2, blockIdx.x & 3, smem);
    } else {
        const int b = blockIdx.x - 64 * NSPL_CLS;
        sim_body<FGDIM, false, NSPL_FG>(b >> 2, b & 3, smem);
    }
}

// ---------------- final deterministic reduction ----------------
__global__ void finalize_kernel(float* __restrict__ out) {
    __shared__ int hist[22];
    __shared__ float red[256][4];
    int tid = threadIdx.x;
    if (tid < 22) hist[tid] = 0;
    __syncthreads();
    for (int i = tid; i < NR; i += 256) atomicAdd(&hist[g_lbl[i] + 1], 1);
    __syncthreads();
    int nnon = NR - hist[0];
    int nfgset = nnon - hist[1];
    float nfg = 0.0f, dfg = 0.0f, ncl = 0.0f, dcl = 0.0f;
    for (int i = tid; i < NR; i += 256) {
        int l = g_lbl[i];
        if (l > 0) {
            float w = g_wgt[i];
            float dnv = 0.0f, nm = 0.0f;
            #pragma unroll
            for (int s = 0; s < NSPL_FG; ++s) {
                dnv += g_pfg[((size_t)s * NR + i) * 2 + 0];
                nm  += g_pfg[((size_t)s * NR + i) * 2 + 1];
            }
            float ef = g_eiif[i];
            dnv -= ef; nm -= ef;
            if (nfgset - 1 > 0) {
                float li = -logf((nm + 1e-8f) / (dnv + 1e-8f));
                nfg += li * w; dfg += w;
            }
            float dc = 0.0f;
            #pragma unroll
            for (int s = 0; s < NSPL_CLS; ++s)
                dc += g_pcl[(size_t)s * NR + i];
            dc -= g_eiic[i];
            float np = (float)(hist[l + 1] - 1);
            if (np > 0.5f && (nnon - 1) > 0) {
                float li = -(g_sp[i] - np * logf(dc)) / np;
                ncl += li * w; dcl += w;
            }
        }
    }
    red[tid][0] = nfg; red[tid][1] = dfg; red[tid][2] = ncl; red[tid][3] = dcl;
    __syncthreads();
    for (int s = 128; s > 0; s >>= 1) {
        if (tid < s) {
            red[tid][0] += red[tid + s][0]; red[tid][1] += red[tid + s][1];
            red[tid][2] += red[tid + s][2]; red[tid][3] += red[tid + s][3];
        }
        __syncthreads();
    }
    if (tid == 0) {
        out[0] = red[0][0] / (red[0][1] + 1e-8f);
        out[1] = red[0][2] / (red[0][3] + 1e-12f);
    }
}

// ---------------- launch ----------------
extern "C" void kernel_launch(void* const* d_in, const int* in_sizes, int n_in,
                              void* d_out, int out_size) {
    const float* roi = (const float*)d_in[0];
    const int*   lab = (const int*)d_in[1];
    const float* iou = (const float*)d_in[2];
    const float* w1f = (const float*)d_in[3];
    const float* b1f = (const float*)d_in[4];
    const float* w2f = (const float*)d_in[5];
    const float* b2f = (const float*)d_in[6];
    const float* w1c = (const float*)d_in[7];
    const float* b1c = (const float*)d_in[8];
    const float* w2c = (const float*)d_in[9];
    const float* b2c = (const float*)d_in[10];

    constexpr int SM_G128 = 2 * (2 * 128 * 144 + 2 * 128 * 144);   // 147456
    constexpr int SMEM_SIM = 3 * 128 * (CLDIM * 2 + 16);           // 104448
    cudaFuncSetAttribute(mma_gemm1,      cudaFuncAttributeMaxDynamicSharedMemorySize, SM_G128);
    cudaFuncSetAttribute(mma_gemm2_all,  cudaFuncAttributeMaxDynamicSharedMemorySize, SM_G128);
    cudaFuncSetAttribute(sim_all_kernel, cudaFuncAttributeMaxDynamicSharedMemorySize, SMEM_SIM);

    prep_conv_kernel<<<CONV_BLKS + NR / 256, 256>>>(roi, w1f, w1c, w2f, w2c, lab, iou);

    mma_gemm1<<<dim3(HD / 128, NR / 128, 2), 256, SM_G128>>>(b1f, b1c);

    mma_gemm2_all<<<128, 256, SM_G128>>>(b2f, b2c);

    class_sum1_kernel<<<CSBLK, CLDIM>>>();
    class_sum2_kernel<<<20, CLDIM>>>();
    row_sp_kernel<<<NR / 8, 256>>>();

    sim_all_kernel<<<64 * NSPL_CLS + 64 * NSPL_FG, 256, SMEM_SIM>>>();

    finalize_kernel<<<1, 256>>>((float*)d_out);
}

// round 15
// speedup vs baseline: 1.0482x; 1.0257x over previous
#include <cuda_runtime.h>
#include <cuda_bf16.h>
#include <math.h>
#include <stdint.h>

#define NR 8192
#define CD 1024
#define HD 256
#define FGDIM 64
#define CLDIM 128
#define NSPL_FG 4
#define NSPL_CLS 4
#define CSBLK 256   // class-sum partial blocks (32 rows each)

// ---------------- device scratch (no allocs allowed) ----------------
__device__ __nv_bfloat16 g_Xh[NR * CD];
__device__ __nv_bfloat16 g_Xl[NR * CD];
__device__ __nv_bfloat16 g_W1fh[HD * CD];
__device__ __nv_bfloat16 g_W1fl[HD * CD];
__device__ __nv_bfloat16 g_W1ch[HD * CD];
__device__ __nv_bfloat16 g_W1cl[HD * CD];
__device__ __nv_bfloat16 g_W2fh[FGDIM * HD];
__device__ __nv_bfloat16 g_W2fl[FGDIM * HD];
__device__ __nv_bfloat16 g_W2ch[CLDIM * HD];
__device__ __nv_bfloat16 g_W2cl[CLDIM * HD];
__device__ __nv_bfloat16 g_Hfh[NR * HD];
__device__ __nv_bfloat16 g_Hfl[NR * HD];
__device__ __nv_bfloat16 g_Hch[NR * HD];
__device__ __nv_bfloat16 g_Hcl[NR * HD];
__device__ float g_Zc[NR * CLDIM];            // CLS fp32 (original row order)
__device__ __nv_bfloat16 g_Zfh[NR * FGDIM];
__device__ __nv_bfloat16 g_Zch[NR * CLDIM];
__device__ float g_pfg[NSPL_FG * NR * 2];     // per split, per row: denom, numer
__device__ float g_pcl[NSPL_CLS * NR];        // per split, per row: denom
__device__ float g_Sp[20 * CSBLK * CLDIM];    // per-class per-block partial sums
__device__ float g_S[20 * CLDIM];
__device__ float g_sp[NR];                    // per-row sum_pos (CLS)
__device__ float g_eiif[NR];                  // per-row self exp (FG, hi*hi)
__device__ float g_eiic[NR];                  // per-row self exp (CLS, hi*hi)
__device__ float g_ssc[NR];                   // per-row ||z||^2 (CLS)
__device__ int   g_lbl[NR];
__device__ float g_fgf[NR];
__device__ float g_vld[NR];
__device__ float g_wgt[NR];

// ---------------- helpers ----------------
__device__ __forceinline__ uint32_t smem_u32(const void* p) {
    uint32_t a;
    asm("{ .reg .u64 t; cvta.to.shared.u64 t, %1; cvt.u32.u64 %0, t; }" : "=r"(a) : "l"(p));
    return a;
}

#define LDSM4(r, addr) \
    asm volatile("ldmatrix.sync.aligned.m8n8.x4.shared.b16 {%0,%1,%2,%3}, [%4];" \
        : "=r"((r)[0]), "=r"((r)[1]), "=r"((r)[2]), "=r"((r)[3]) : "r"(addr))

#define MMA16816(d, a, b0, b1) \
    asm volatile("mma.sync.aligned.m16n8k16.row.col.f32.bf16.bf16.f32 " \
        "{%0,%1,%2,%3},{%4,%5,%6,%7},{%8,%9},{%0,%1,%2,%3};" \
        : "+f"((d)[0]), "+f"((d)[1]), "+f"((d)[2]), "+f"((d)[3]) \
        : "r"((a)[0]), "r"((a)[1]), "r"((a)[2]), "r"((a)[3]), "r"(b0), "r"(b1))

// ---------------- packed f32x2 ops ----------------
__device__ __forceinline__ uint64_t pk2(float a, float b) {
    uint64_t r; asm("mov.b64 %0, {%1, %2};" : "=l"(r) : "f"(a), "f"(b)); return r;
}
__device__ __forceinline__ void upk2(uint64_t v, float& a, float& b) {
    asm("mov.b64 {%0, %1}, %2;" : "=f"(a), "=f"(b) : "l"(v));
}
__device__ __forceinline__ uint64_t fma2(uint64_t a, uint64_t b, uint64_t c) {
    uint64_t d; asm("fma.rn.f32x2 %0, %1, %2, %3;" : "=l"(d) : "l"(a), "l"(b), "l"(c)); return d;
}
__device__ __forceinline__ uint64_t add2(uint64_t a, uint64_t b) {
    uint64_t d; asm("add.rn.f32x2 %0, %1, %2;" : "=l"(d) : "l"(a), "l"(b)); return d;
}
__device__ __forceinline__ uint64_t mul2(uint64_t a, uint64_t b) {
    uint64_t d; asm("mul.rn.f32x2 %0, %1, %2;" : "=l"(d) : "l"(a), "l"(b)); return d;
}

// packed exp(5x): range reduce + quadratic 2^f on [-0.5, 0.5]
// (max rel err ~0.17%, ~-8e-5 at f=0; common-scale bias cancels in the loss ratios)
__device__ __forceinline__ uint64_t fexp5_2(uint64_t x2) {
    const float KE = 7.2134752044448169f;   // 5 * log2(e)
    const float SH = 12582912.0f;           // 1.5 * 2^23
    const uint64_t KE2 = pk2(KE, KE);
    const uint64_t SH2 = pk2(SH, SH);
    const uint64_t N12 = pk2(-1.0f, -1.0f);
    uint64_t z2 = fma2(x2, KE2, SH2);
    float zl, zh; upk2(z2, zl, zh);
    int e0 = (__float_as_int(zl) - 0x4B3FFF81) << 23;
    int e1 = (__float_as_int(zh) - 0x4B3FFF81) << 23;
    uint64_t nr2 = fma2(z2, N12, SH2);
    uint64_t f2 = fma2(x2, KE2, nr2);
    uint64_t p = pk2(0.24264f, 0.24264f);
    p = fma2(p, f2, pk2(0.70354f, 0.70354f));
    p = fma2(p, f2, pk2(0.99992f, 0.99992f));
    return mul2(p, pk2(__int_as_float(e0), __int_as_float(e1)));
}

// scalar exp(5x), degree-4
__device__ __forceinline__ float fexp5(float x) {
    const float KE = 7.2134752044448169f;
    const float SH = 12582912.0f;
    float z = fmaf(x, KE, SH);
    int   ei = __float_as_int(z);
    float r = z - SH;
    float f = fmaf(x, KE, -r);
    float p = 9.6181291076284771e-3f;
    p = fmaf(p, f, 5.5504108664821580e-2f);
    p = fmaf(p, f, 2.4022650695910071e-1f);
    p = fmaf(p, f, 6.9314718055994531e-1f);
    p = fmaf(p, f, 1.0f);
    return p * __int_as_float((ei - 0x4B400000 + 127) << 23);
}

// ---------------- merged prep + hi/lo conversions (one launch) ----------------
#define SEG_X   2097152
#define SEG_W1F 2162688
#define SEG_W1C 2228224
#define SEG_W2F 2232320
#define SEG_W2C 2240512
#define CONV_BLKS 8752

__global__ void prep_conv_kernel(const float* __restrict__ roi,
                                 const float* __restrict__ w1f, const float* __restrict__ w1c,
                                 const float* __restrict__ w2f, const float* __restrict__ w2c,
                                 const int* __restrict__ lraw, const float* __restrict__ ious) {
    if (blockIdx.x >= CONV_BLKS) {
        int i = (blockIdx.x - CONV_BLKS) * 256 + threadIdx.x;
        bool is64 = true;
        #pragma unroll 1
        for (int p = 0; p < 32; ++p) {
            int lo = lraw[2 * p], hi = lraw[2 * p + 1];
            bool ok = (hi == 0 && lo >= 0) || (hi == -1 && lo < 0);
            if (!ok) { is64 = false; break; }
        }
        int l = is64 ? (int)(((const long long*)lraw)[i]) : lraw[i];
        g_lbl[i] = l;
        g_fgf[i] = (l > 0) ? 1.0f : 0.0f;
        g_vld[i] = (l != -1) ? 1.0f : 0.0f;
        float u = ious[i];
        g_wgt[i] = (u > 0.5f) ? u : 0.0f;
        return;
    }
    int i = blockIdx.x * 256 + threadIdx.x;
    const float* s; __nv_bfloat16 *h, *l; int base;
    if (i < SEG_X)        { s = roi; h = g_Xh;   l = g_Xl;   base = 0; }
    else if (i < SEG_W1F) { s = w1f; h = g_W1fh; l = g_W1fl; base = SEG_X; }
    else if (i < SEG_W1C) { s = w1c; h = g_W1ch; l = g_W1cl; base = SEG_W1F; }
    else if (i < SEG_W2F) { s = w2f; h = g_W2fh; l = g_W2fl; base = SEG_W1C; }
    else                  { s = w2c; h = g_W2ch; l = g_W2cl; base = SEG_W2F; }
    int j = i - base;
    float4 v = ((const float4*)s)[j];
    __nv_bfloat162 h0, h1, l0, l1;
    h0.x = __float2bfloat16(v.x); h0.y = __float2bfloat16(v.y);
    h1.x = __float2bfloat16(v.z); h1.y = __float2bfloat16(v.w);
    l0.x = __float2bfloat16(v.x - __bfloat162float(h0.x));
    l0.y = __float2bfloat16(v.y - __bfloat162float(h0.y));
    l1.x = __float2bfloat16(v.z - __bfloat162float(h1.x));
    l1.y = __float2bfloat16(v.w - __bfloat162float(h1.y));
    ((__nv_bfloat162*)h)[j * 2] = h0; ((__nv_bfloat162*)h)[j * 2 + 1] = h1;
    ((__nv_bfloat162*)l)[j * 2] = l0; ((__nv_bfloat162*)l)[j * 2 + 1] = l1;
}

// ---------------- cp.async bf16 tile loader (BK=64, padded stride 144B) ----------------
__device__ __forceinline__ void ld_tile64(uint32_t dst, const __nv_bfloat16* __restrict__ src,
                                          int rows, int K, int tid) {
    #pragma unroll 4
    for (int i = tid; i < rows * 8; i += 256) {
        int r = i >> 3, c = i & 7;
        asm volatile("cp.async.cg.shared.global [%0], [%1], 16;"
                     :: "r"(dst + r * 144 + c * 16), "l"(src + (size_t)r * K + c * 8) : "memory");
    }
}

// ---------------- layer-1 MMA GEMM (3-chain, single-buffer, occ 2) ----------------
__global__ __launch_bounds__(256, 2) void mma_gemm1(
    const float* __restrict__ bias0, const float* __restrict__ bias1) {
    constexpr int BN = 128, SA = 144;
    constexpr int ATS = 128 * SA;
    constexpr int BTS = BN * SA;
    constexpr int NG = BN / 32, NF = 2 * NG;
    constexpr int N = HD, K = CD;

    extern __shared__ char smem[];
    uint32_t sb = smem_u32(smem);
    const int tid = threadIdx.x, wid = tid >> 5, lane = tid & 31;
    const int wm = wid & 3, wn = wid >> 2;
    const int z = blockIdx.z;
    const int bm = blockIdx.y * 128, bn = blockIdx.x * BN;

    const __nv_bfloat16* Ah = g_Xh;
    const __nv_bfloat16* Al = g_Xl;
    const __nv_bfloat16* Wh = z ? g_W1ch : g_W1fh;
    const __nv_bfloat16* Wl = z ? g_W1cl : g_W1fl;
    const float* bias = z ? bias1 : bias0;
    __nv_bfloat16* oh = z ? g_Hch : g_Hfh;
    __nv_bfloat16* ol = z ? g_Hcl : g_Hfl;

    const int KC = K >> 6;

    float acc[2][NF][4];
    #pragma unroll
    for (int ma = 0; ma < 2; ++ma)
        #pragma unroll
        for (int nf = 0; nf < NF; ++nf)
            #pragma unroll
            for (int e = 0; e < 4; ++e) acc[ma][nf][e] = 0.0f;

    const uint32_t a_off = (uint32_t)((wm * 32 + (lane & 15)) * SA + (lane >> 4) * 16);
    const uint32_t b_off = (uint32_t)((wn * (BN / 2) + ((lane >> 4) << 3) + (lane & 7)) * SA + ((lane >> 3) & 1) * 16);

    for (int kc = 0; kc < KC; ++kc) {
        const int ko = kc * 64;
        if (kc) __syncthreads();     // previous compute done before overwrite
        ld_tile64(sb, Ah + (size_t)bm * K + ko, 128, K, tid);
        ld_tile64(sb + ATS, Al + (size_t)bm * K + ko, 128, K, tid);
        ld_tile64(sb + 2 * ATS, Wh + (size_t)bn * K + ko, BN, K, tid);
        ld_tile64(sb + 2 * ATS + BTS, Wl + (size_t)bn * K + ko, BN, K, tid);
        asm volatile("cp.async.commit_group;" ::: "memory");
        asm volatile("cp.async.wait_group 0;" ::: "memory");
        __syncthreads();

        #pragma unroll
        for (int ks = 0; ks < 4; ++ks) {
            const uint32_t kb = ks * 32;
            uint32_t a_h[2][4], a_l[2][4], b_h[NG][4], b_l[NG][4];
            #pragma unroll
            for (int ma = 0; ma < 2; ++ma) {
                LDSM4(a_h[ma], sb + a_off + ma * 16 * SA + kb);
                LDSM4(a_l[ma], sb + ATS + a_off + ma * 16 * SA + kb);
            }
            #pragma unroll
            for (int g = 0; g < NG; ++g) {
                LDSM4(b_h[g], sb + 2 * ATS + b_off + g * 16 * SA + kb);
                LDSM4(b_l[g], sb + 2 * ATS + BTS + b_off + g * 16 * SA + kb);
            }
            #pragma unroll
            for (int ma = 0; ma < 2; ++ma)
                #pragma unroll
                for (int g = 0; g < NG; ++g) {
                    MMA16816(acc[ma][2 * g],     a_h[ma], b_h[g][0], b_h[g][1]);
                    MMA16816(acc[ma][2 * g + 1], a_h[ma], b_h[g][2], b_h[g][3]);
                    MMA16816(acc[ma][2 * g],     a_h[ma], b_l[g][0], b_l[g][1]);
                    MMA16816(acc[ma][2 * g + 1], a_h[ma], b_l[g][2], b_l[g][3]);
                    MMA16816(acc[ma][2 * g],     a_l[ma], b_h[g][0], b_h[g][1]);
                    MMA16816(acc[ma][2 * g + 1], a_l[ma], b_h[g][2], b_h[g][3]);
                }
        }
    }

    #pragma unroll
    for (int ma = 0; ma < 2; ++ma)
        #pragma unroll
        for (int nf = 0; nf < NF; ++nf)
            #pragma unroll
            for (int rp = 0; rp < 2; ++rp) {
                const int r = bm + wm * 32 + ma * 16 + rp * 8 + (lane >> 2);
                const int c = bn + wn * (BN / 2) + nf * 8 + (lane & 3) * 2;
                float2 bb = *(const float2*)(bias + c);
                float v0 = fmaxf(acc[ma][nf][rp * 2 + 0] + bb.x, 0.0f);
                float v1 = fmaxf(acc[ma][nf][rp * 2 + 1] + bb.y, 0.0f);
                __nv_bfloat162 hv, lv;
                hv.x = __float2bfloat16(v0); hv.y = __float2bfloat16(v1);
                lv.x = __float2bfloat16(v0 - __bfloat162float(hv.x));
                lv.y = __float2bfloat16(v1 - __bfloat162float(hv.y));
                *(__nv_bfloat162*)(oh + (size_t)r * N + c) = hv;
                *(__nv_bfloat162*)(ol + (size_t)r * N + c) = lv;
            }
}

// ---------------- layer-2 body: single-buffer GEMM + fused normalize + hi-split + eii/ss ----------------
template<int BN>
__device__ __forceinline__ void gemm2_body(
    const __nv_bfloat16* __restrict__ Ah, const __nv_bfloat16* __restrict__ Al,
    const __nv_bfloat16* __restrict__ Wh, const __nv_bfloat16* __restrict__ Wl,
    const float* __restrict__ bias,
    float* __restrict__ Zout, __nv_bfloat16* __restrict__ Oh,
    float* __restrict__ eii, float* __restrict__ ssout,
    int bm, char* smem) {
    constexpr int SA = 144;
    constexpr int ATS = 128 * SA;
    constexpr int BTS = BN * SA;
    constexpr int NG = BN / 32, NF = 2 * NG;
    constexpr int K = HD;
    constexpr int ZS = BN + 4;

    uint32_t sb = smem_u32(smem);
    float* zbuf = (float*)smem;
    const int tid = threadIdx.x, wid = tid >> 5, lane = tid & 31;
    const int wm = wid & 3, wn = wid >> 2;

    const int KC = K >> 6;

    float acc[2][NF][4];
    #pragma unroll
    for (int ma = 0; ma < 2; ++ma)
        #pragma unroll
        for (int nf = 0; nf < NF; ++nf)
            #pragma unroll
            for (int e = 0; e < 4; ++e) acc[ma][nf][e] = 0.0f;

    const uint32_t a_off = (uint32_t)((wm * 32 + (lane & 15)) * SA + (lane >> 4) * 16);
    const uint32_t b_off = (uint32_t)((wn * (BN / 2) + ((lane >> 4) << 3) + (lane & 7)) * SA + ((lane >> 3) & 1) * 16);

    for (int kc = 0; kc < KC; ++kc) {
        const int ko = kc * 64;
        if (kc) __syncthreads();
        ld_tile64(sb, Ah + (size_t)bm * K + ko, 128, K, tid);
        ld_tile64(sb + ATS, Al + (size_t)bm * K + ko, 128, K, tid);
        ld_tile64(sb + 2 * ATS, Wh + ko, BN, K, tid);
        ld_tile64(sb + 2 * ATS + BTS, Wl + ko, BN, K, tid);
        asm volatile("cp.async.commit_group;" ::: "memory");
        asm volatile("cp.async.wait_group 0;" ::: "memory");
        __syncthreads();

        #pragma unroll
        for (int ks = 0; ks < 4; ++ks) {
            const uint32_t kb = ks * 32;
            uint32_t a_h[2][4], a_l[2][4], b_h[NG][4], b_l[NG][4];
            #pragma unroll
            for (int ma = 0; ma < 2; ++ma) {
                LDSM4(a_h[ma], sb + a_off + ma * 16 * SA + kb);
                LDSM4(a_l[ma], sb + ATS + a_off + ma * 16 * SA + kb);
            }
            #pragma unroll
            for (int g = 0; g < NG; ++g) {
                LDSM4(b_h[g], sb + 2 * ATS + b_off + g * 16 * SA + kb);
                LDSM4(b_l[g], sb + 2 * ATS + BTS + b_off + g * 16 * SA + kb);
            }
            #pragma unroll
            for (int ma = 0; ma < 2; ++ma)
                #pragma unroll
                for (int g = 0; g < NG; ++g) {
                    MMA16816(acc[ma][2 * g],     a_h[ma], b_h[g][0], b_h[g][1]);
                    MMA16816(acc[ma][2 * g + 1], a_h[ma], b_h[g][2], b_h[g][3]);
                    MMA16816(acc[ma][2 * g],     a_h[ma], b_l[g][0], b_l[g][1]);
                    MMA16816(acc[ma][2 * g + 1], a_h[ma], b_l[g][2], b_l[g][3]);
                    MMA16816(acc[ma][2 * g],     a_l[ma], b_h[g][0], b_h[g][1]);
                    MMA16816(acc[ma][2 * g + 1], a_l[ma], b_h[g][2], b_h[g][3]);
                }
        }
    }
    __syncthreads();   // all ldsm done before zbuf overwrites smem

    #pragma unroll
    for (int ma = 0; ma < 2; ++ma)
        #pragma unroll
        for (int nf = 0; nf < NF; ++nf)
            #pragma unroll
            for (int rp = 0; rp < 2; ++rp) {
                const int r = wm * 32 + ma * 16 + rp * 8 + (lane >> 2);
                const int c = wn * (BN / 2) + nf * 8 + (lane & 3) * 2;
                float2 bb = *(const float2*)(bias + c);
                zbuf[r * ZS + c] = acc[ma][nf][rp * 2 + 0] + bb.x;
                zbuf[r * ZS + c + 1] = acc[ma][nf][rp * 2 + 1] + bb.y;
            }
    __syncthreads();

    constexpr int CE = BN / 32;
    for (int rr = 0; rr < 16; ++rr) {
        const int r = wid * 16 + rr;
        const int grow = bm + r;
        float v[CE];
        float ss = 0.0f;
        #pragma unroll
        for (int q = 0; q < CE; ++q) { v[q] = zbuf[r * ZS + lane + q * 32]; ss += v[q] * v[q]; }
        #pragma unroll
        for (int o = 16; o; o >>= 1) ss += __shfl_xor_sync(0xffffffffu, ss, o);
        const float inv = 1.0f / fmaxf(sqrtf(ss), 1e-8f);
        float hh = 0.0f;
        #pragma unroll
        for (int q = 0; q < CE; ++q) {
            float zv = v[q] * inv;
            if (Zout) Zout[(size_t)grow * BN + lane + q * 32] = zv;
            __nv_bfloat16 h = __float2bfloat16(zv);
            Oh[(size_t)grow * BN + lane + q * 32] = h;
            float hf = __bfloat162float(h);
            hh = fmaf(hf, hf, hh);
        }
        #pragma unroll
        for (int o = 16; o; o >>= 1) hh += __shfl_xor_sync(0xffffffffu, hh, o);
        if (lane == 0) {
            eii[grow] = fexp5(hh);
            if (ssout) ssout[grow] = ss * inv * inv;
        }
    }
}

__global__ __launch_bounds__(256, 2) void mma_gemm2_all(
    const float* __restrict__ b2f, const float* __restrict__ b2c) {
    extern __shared__ char smem[];
    if (blockIdx.x < 64)
        gemm2_body<FGDIM>(g_Hfh, g_Hfl, g_W2fh, g_W2fl, b2f,
                          nullptr, g_Zfh, g_eiif, nullptr,
                          blockIdx.x * 128, smem);
    else
        gemm2_body<CLDIM>(g_Hch, g_Hcl, g_W2ch, g_W2cl, b2c,
                          g_Zc, g_Zch, g_eiic, g_ssc,
                          (blockIdx.x - 64) * 128, smem);
}

// ---------------- per-class z sums: batch-4 prefetch row-pass ----------------
__global__ void class_sum1_kernel() {     // grid CSBLK (256), block CLDIM (128), 32 rows each
    __shared__ float sh[20][CLDIM];
    const int d = threadIdx.x;
    #pragma unroll
    for (int c = 0; c < 20; ++c) sh[c][d] = 0.0f;
    const int i0 = blockIdx.x * (NR / CSBLK);
    constexpr int NB = (NR / CSBLK) / 4;   // 8 batches of 4 rows
    int   lc[4];
    float vc[4];
    #pragma unroll
    for (int k = 0; k < 4; ++k) {
        lc[k] = g_lbl[i0 + k];
        vc[k] = g_Zc[(size_t)(i0 + k) * CLDIM + d];
    }
    #pragma unroll 1
    for (int b = 0; b < NB; ++b) {
        int   ln[4];
        float vn[4];
        if (b + 1 < NB) {
            const int ib = i0 + (b + 1) * 4;
            #pragma unroll
            for (int k = 0; k < 4; ++k) {
                ln[k] = g_lbl[ib + k];
                vn[k] = g_Zc[(size_t)(ib + k) * CLDIM + d];
            }
        }
        #pragma unroll
        for (int k = 0; k < 4; ++k)
            if (lc[k] > 0) sh[lc[k] - 1][d] += vc[k];
        #pragma unroll
        for (int k = 0; k < 4; ++k) { lc[k] = ln[k]; vc[k] = vn[k]; }
    }
    #pragma unroll
    for (int c = 0; c < 20; ++c)
        g_Sp[((size_t)c * CSBLK + blockIdx.x) * CLDIM + d] = sh[c][d];
}
__global__ void class_sum2_kernel() {     // grid 20, block CLDIM
    float s = 0.0f;
    #pragma unroll 8
    for (int g = 0; g < CSBLK; ++g)
        s += g_Sp[((size_t)blockIdx.x * CSBLK + g) * CLDIM + threadIdx.x];
    g_S[blockIdx.x * CLDIM + threadIdx.x] = s;
}

// ---------------- per-row sum_pos for CLS (warp per row) ----------------
__global__ void row_sp_kernel() {
    int row = blockIdx.x * 8 + (threadIdx.x >> 5);
    int lane = threadIdx.x & 31;
    int l = g_lbl[row];
    const float* S = g_S + (l > 0 ? (l - 1) : 0) * CLDIM;
    float sd = 0.0f;
    #pragma unroll
    for (int c = lane; c < CLDIM; c += 32)
        sd += g_Zc[(size_t)row * CLDIM + c] * S[c];
    #pragma unroll
    for (int o = 16; o; o >>= 1) sd += __shfl_xor_sync(0xffffffffu, sd, o);
    if (lane == 0) g_sp[row] = 5.0f * (sd - g_ssc[row]);
}

// ---------------- cp.async tile loader for sim (full K resident) ----------------
template<int KD>
__device__ __forceinline__ void load_tile(uint32_t dst, const __nv_bfloat16* __restrict__ src, int tid) {
    constexpr int CPR = KD / 8;
    constexpr int SA = KD * 2 + 16;
    #pragma unroll
    for (int i = tid; i < 128 * CPR; i += 256) {
        int r = i / CPR, c = i % CPR;
        asm volatile("cp.async.cg.shared.global [%0], [%1], 16;"
                     :: "r"(dst + r * SA + c * 16), "l"(src + (size_t)r * KD + c * 8) : "memory");
    }
}

// ---------------- sim body (1-chain hi*hi, flag-load packed epilogue) ----------------
template<int KD, bool CLS, int NSPLT>
__device__ __forceinline__ void sim_body(int bx, int by, char* smem) {
    constexpr int SA = KD * 2 + 16;
    constexpr int TSZ = 128 * SA;
    constexpr int SLAB = NR / NSPLT;
    constexpr int TCOLS = SLAB / 128;
    constexpr int KSTEPS = KD / 16;
    constexpr int B_OFF = TSZ;

    uint32_t sb = smem_u32(smem);
    const int tid = threadIdx.x, wid = tid >> 5, lane = tid & 31;
    const int wm = wid & 3, wn = wid >> 2;
    const int bm = bx * 128;
    const int c0 = by * SLAB;
    const __nv_bfloat16* Zh = CLS ? g_Zch : g_Zfh;
    const float* flg = CLS ? g_vld : g_fgf;

    load_tile<KD>(sb, Zh + (size_t)bm * KD, tid);
    load_tile<KD>(sb + B_OFF, Zh + (size_t)c0 * KD, tid);
    asm volatile("cp.async.commit_group;" ::: "memory");

    uint64_t dn2[2][2] = {{0ull, 0ull}, {0ull, 0ull}};
    uint64_t x12[2][2] = {{0ull, 0ull}, {0ull, 0ull}};

    const uint32_t a_off = (uint32_t)((wm * 32 + (lane & 15)) * SA + (lane >> 4) * 16);
    const uint32_t b_off = (uint32_t)((wn * 64 + ((lane >> 4) << 3) + (lane & 7)) * SA + ((lane >> 3) & 1) * 16);

    float acc[2][8][4];
    #pragma unroll
    for (int ma = 0; ma < 2; ++ma)
        #pragma unroll
        for (int na = 0; na < 8; ++na)
            #pragma unroll
            for (int e = 0; e < 4; ++e) acc[ma][na][e] = 0.0f;

    asm volatile("cp.async.wait_group 0;" ::: "memory");
    __syncthreads();

    for (int t = 0; t < TCOLS; ++t) {
        const uint32_t bcur = sb + B_OFF + (t & 1) * TSZ;
        if (t + 1 < TCOLS) {
            load_tile<KD>(sb + B_OFF + ((t + 1) & 1) * TSZ,
                          Zh + (size_t)(c0 + (t + 1) * 128) * KD, tid);
            asm volatile("cp.async.commit_group;" ::: "memory");
        }

        #pragma unroll
        for (int ks = 0; ks < KSTEPS; ++ks) {
            uint32_t a_h[2][4], b_h[4][4];
            const uint32_t kb = ks * 32;
            #pragma unroll
            for (int ma = 0; ma < 2; ++ma)
                LDSM4(a_h[ma], sb + a_off + ma * 16 * SA + kb);
            #pragma unroll
            for (int g = 0; g < 4; ++g)
                LDSM4(b_h[g], bcur + b_off + g * 16 * SA + kb);
            #pragma unroll
            for (int ma = 0; ma < 2; ++ma)
                #pragma unroll
                for (int g = 0; g < 4; ++g) {
                    MMA16816(acc[ma][2 * g],     a_h[ma], b_h[g][0], b_h[g][1]);
                    MMA16816(acc[ma][2 * g + 1], a_h[ma], b_h[g][2], b_h[g][3]);
                }
        }

        const int tb = c0 + t * 128;
        #pragma unroll
        for (int na = 0; na < 8; ++na) {
            const int cA = wn * 64 + na * 8 + (lane & 3) * 2;
            const float2 lp = *(const float2*)(flg + tb + cA);
            const uint64_t fl2 = pk2(lp.x, lp.y);
            #pragma unroll
            for (int ma = 0; ma < 2; ++ma) {
                float* c = acc[ma][na];
                uint64_t ea = fexp5_2(pk2(c[0], c[1]));
                uint64_t eb = fexp5_2(pk2(c[2], c[3]));
                if (CLS) {
                    dn2[ma][0] = fma2(ea, fl2, dn2[ma][0]);
                    dn2[ma][1] = fma2(eb, fl2, dn2[ma][1]);
                } else {
                    dn2[ma][0] = add2(dn2[ma][0], ea);
                    dn2[ma][1] = add2(dn2[ma][1], eb);
                    x12[ma][0] = fma2(ea, fl2, x12[ma][0]);
                    x12[ma][1] = fma2(eb, fl2, x12[ma][1]);
                }
                c[0] = 0.0f; c[1] = 0.0f; c[2] = 0.0f; c[3] = 0.0f;
            }
        }

        if (t + 1 < TCOLS) {
            asm volatile("cp.async.wait_group 0;" ::: "memory");
        }
        __syncthreads();
    }

    float dn[2][2], x1[2][2];
    #pragma unroll
    for (int ma = 0; ma < 2; ++ma)
        #pragma unroll
        for (int rp = 0; rp < 2; ++rp) {
            float a, b;
            upk2(dn2[ma][rp], a, b); dn[ma][rp] = a + b;
            upk2(x12[ma][rp], a, b); x1[ma][rp] = a + b;
            #pragma unroll
            for (int o = 1; o <= 2; o <<= 1) {
                dn[ma][rp] += __shfl_xor_sync(0xffffffffu, dn[ma][rp], o);
                if (!CLS) x1[ma][rp] += __shfl_xor_sync(0xffffffffu, x1[ma][rp], o);
            }
        }

    float* red = (float*)smem;
    __syncthreads();
    if (wn == 1 && (lane & 3) == 0) {
        #pragma unroll
        for (int ma = 0; ma < 2; ++ma)
            #pragma unroll
            for (int rp = 0; rp < 2; ++rp) {
                int rl = wm * 32 + ma * 16 + rp * 8 + (lane >> 2);
                red[rl * 2 + 0] = dn[ma][rp];
                red[rl * 2 + 1] = x1[ma][rp];
            }
    }
    __syncthreads();
    if (wn == 0 && (lane & 3) == 0) {
        const int s = by;
        #pragma unroll
        for (int ma = 0; ma < 2; ++ma)
            #pragma unroll
            for (int rp = 0; rp < 2; ++rp) {
                int rl = wm * 32 + ma * 16 + rp * 8 + (lane >> 2);
                float a = dn[ma][rp] + red[rl * 2 + 0];
                int g = bm + rl;
                if (CLS) {
                    g_pcl[(size_t)s * NR + g] = a;
                } else {
                    float b = x1[ma][rp] + red[rl * 2 + 1];
                    g_pfg[((size_t)s * NR + g) * 2 + 0] = a;
                    g_pfg[((size_t)s * NR + g) * 2 + 1] = b;
                }
            }
    }
}

__global__ __launch_bounds__(256, 2) void sim_all_kernel() {
    extern __shared__ char smem[];
    if (blockIdx.x < 64 * NSPL_CLS) {
        sim_body<CLDIM, true, NSPL_CLS>(blockIdx.x >> 2, blockIdx.x & 3, smem);
    } else {
        const int b = blockIdx.x - 64 * NSPL_CLS;
        sim_body<FGDIM, false, NSPL_FG>(b >> 2, b & 3, smem);
    }
}

// ---------------- final deterministic reduction ----------------
__global__ void finalize_kernel(float* __restrict__ out) {
    __shared__ int hist[22];
    __shared__ float red[256][4];
    int tid = threadIdx.x;
    if (tid < 22) hist[tid] = 0;
    __syncthreads();
    for (int i = tid; i < NR; i += 256) atomicAdd(&hist[g_lbl[i] + 1], 1);
    __syncthreads();
    int nnon = NR - hist[0];
    int nfgset = nnon - hist[1];
    float nfg = 0.0f, dfg = 0.0f, ncl = 0.0f, dcl = 0.0f;
    for (int i = tid; i < NR; i += 256) {
        int l = g_lbl[i];
        if (l > 0) {
            float w = g_wgt[i];
            float dnv = 0.0f, nm = 0.0f;
            #pragma unroll
            for (int s = 0; s < NSPL_FG; ++s) {
                dnv += g_pfg[((size_t)s * NR + i) * 2 + 0];
                nm  += g_pfg[((size_t)s * NR + i) * 2 + 1];
            }
            float ef = g_eiif[i];
            dnv -= ef; nm -= ef;
            if (nfgset - 1 > 0) {
                float li = -logf((nm + 1e-8f) / (dnv + 1e-8f));
                nfg += li * w; dfg += w;
            }
            float dc = 0.0f;
            #pragma unroll
            for (int s = 0; s < NSPL_CLS; ++s)
                dc += g_pcl[(size_t)s * NR + i];
            dc -= g_eiic[i];
            float np = (float)(hist[l + 1] - 1);
            if (np > 0.5f && (nnon - 1) > 0) {
                float li = -(g_sp[i] - np * logf(dc)) / np;
                ncl += li * w; dcl += w;
            }
        }
    }
    red[tid][0] = nfg; red[tid][1] = dfg; red[tid][2] = ncl; red[tid][3] = dcl;
    __syncthreads();
    for (int s = 128; s > 0; s >>= 1) {
        if (tid < s) {
            red[tid][0] += red[tid + s][0]; red[tid][1] += red[tid + s][1];
            red[tid][2] += red[tid + s][2]; red[tid][3] += red[tid + s][3];
        }
        __syncthreads();
    }
    if (tid == 0) {
        out[0] = red[0][0] / (red[0][1] + 1e-8f);
        out[1] = red[0][2] / (red[0][3] + 1e-12f);
    }
}

// ---------------- launch ----------------
extern "C" void kernel_launch(void* const* d_in, const int* in_sizes, int n_in,
                              void* d_out, int out_size) {
    const float* roi = (const float*)d_in[0];
    const int*   lab = (const int*)d_in[1];
    const float* iou = (const float*)d_in[2];
    const float* w1f = (const float*)d_in[3];
    const float* b1f = (const float*)d_in[4];
    const float* w2f = (const float*)d_in[5];
    const float* b2f = (const float*)d_in[6];
    const float* w1c = (const float*)d_in[7];
    const float* b1c = (const float*)d_in[8];
    const float* w2c = (const float*)d_in[9];
    const float* b2c = (const float*)d_in[10];

    constexpr int SM_G1 = 2 * 128 * 144 + 2 * 128 * 144;   // 73728, single stage → occ 2
    constexpr int SMEM_SIM = 3 * 128 * (CLDIM * 2 + 16);   // 104448
    cudaFuncSetAttribute(mma_gemm1,      cudaFuncAttributeMaxDynamicSharedMemorySize, SM_G1);
    cudaFuncSetAttribute(mma_gemm2_all,  cudaFuncAttributeMaxDynamicSharedMemorySize, SM_G1);
    cudaFuncSetAttribute(sim_all_kernel, cudaFuncAttributeMaxDynamicSharedMemorySize, SMEM_SIM);

    prep_conv_kernel<<<CONV_BLKS + NR / 256, 256>>>(roi, w1f, w1c, w2f, w2c, lab, iou);

    mma_gemm1<<<dim3(HD / 128, NR / 128, 2), 256, SM_G1>>>(b1f, b1c);

    mma_gemm2_all<<<128, 256, SM_G1>>>(b2f, b2c);

    class_sum1_kernel<<<CSBLK, CLDIM>>>();
    class_sum2_kernel<<<20, CLDIM>>>();
    row_sp_kernel<<<NR / 8, 256>>>();

    sim_all_kernel<<<64 * NSPL_CLS + 64 * NSPL_FG, 256, SMEM_SIM>>>();

    finalize_kernel<<<1, 256>>>((float*)d_out);
}

// round 16
// speedup vs baseline: 1.0992x; 1.0486x over previous
#include <cuda_runtime.h>
#include <cuda_bf16.h>
#include <math.h>
#include <stdint.h>

#define NR 8192
#define CD 1024
#define HD 256
#define FGDIM 64
#define CLDIM 128
#define NSPL_FG 4
#define NSPL_CLS 4
#define CSBLK 256   // class-sum partial blocks (32 rows each)

// ---------------- device scratch (no allocs allowed) ----------------
__device__ __nv_bfloat16 g_Xh[NR * CD];
__device__ __nv_bfloat16 g_Xl[NR * CD];
__device__ __nv_bfloat16 g_W1fh[HD * CD];
__device__ __nv_bfloat16 g_W1fl[HD * CD];
__device__ __nv_bfloat16 g_W1ch[HD * CD];
__device__ __nv_bfloat16 g_W1cl[HD * CD];
__device__ __nv_bfloat16 g_W2fh[FGDIM * HD];
__device__ __nv_bfloat16 g_W2fl[FGDIM * HD];
__device__ __nv_bfloat16 g_W2ch[CLDIM * HD];
__device__ __nv_bfloat16 g_W2cl[CLDIM * HD];
__device__ __nv_bfloat16 g_Hfh[NR * HD];
__device__ __nv_bfloat16 g_Hfl[NR * HD];
__device__ __nv_bfloat16 g_Hch[NR * HD];
__device__ __nv_bfloat16 g_Hcl[NR * HD];
__device__ float g_Zc[NR * CLDIM];            // CLS fp32 (original row order)
__device__ __nv_bfloat16 g_Zfh[NR * FGDIM];
__device__ __nv_bfloat16 g_Zch[NR * CLDIM];
__device__ float g_pfg[NSPL_FG * NR * 2];     // per split, per row: denom, numer
__device__ float g_pcl[NSPL_CLS * NR];        // per split, per row: denom
__device__ float g_Sp[20 * CSBLK * CLDIM];    // per-class per-block partial sums
__device__ float g_S[20 * CLDIM];
__device__ float g_sp[NR];                    // per-row sum_pos (CLS)
__device__ float g_eiif[NR];                  // per-row self exp (FG, hi*hi)
__device__ float g_eiic[NR];                  // per-row self exp (CLS, hi*hi)
__device__ float g_ssc[NR];                   // per-row ||z||^2 (CLS)
__device__ int   g_lbl[NR];
__device__ float g_fgf[NR];
__device__ float g_vld[NR];
__device__ float g_wgt[NR];

// ---------------- helpers ----------------
__device__ __forceinline__ uint32_t smem_u32(const void* p) {
    uint32_t a;
    asm("{ .reg .u64 t; cvta.to.shared.u64 t, %1; cvt.u32.u64 %0, t; }" : "=r"(a) : "l"(p));
    return a;
}

#define LDSM4(r, addr) \
    asm volatile("ldmatrix.sync.aligned.m8n8.x4.shared.b16 {%0,%1,%2,%3}, [%4];" \
        : "=r"((r)[0]), "=r"((r)[1]), "=r"((r)[2]), "=r"((r)[3]) : "r"(addr))

#define MMA16816(d, a, b0, b1) \
    asm volatile("mma.sync.aligned.m16n8k16.row.col.f32.bf16.bf16.f32 " \
        "{%0,%1,%2,%3},{%4,%5,%6,%7},{%8,%9},{%0,%1,%2,%3};" \
        : "+f"((d)[0]), "+f"((d)[1]), "+f"((d)[2]), "+f"((d)[3]) \
        : "r"((a)[0]), "r"((a)[1]), "r"((a)[2]), "r"((a)[3]), "r"(b0), "r"(b1))

// ---------------- packed f32x2 ops ----------------
__device__ __forceinline__ uint64_t pk2(float a, float b) {
    uint64_t r; asm("mov.b64 %0, {%1, %2};" : "=l"(r) : "f"(a), "f"(b)); return r;
}
__device__ __forceinline__ void upk2(uint64_t v, float& a, float& b) {
    asm("mov.b64 {%0, %1}, %2;" : "=f"(a), "=f"(b) : "l"(v));
}
__device__ __forceinline__ uint64_t fma2(uint64_t a, uint64_t b, uint64_t c) {
    uint64_t d; asm("fma.rn.f32x2 %0, %1, %2, %3;" : "=l"(d) : "l"(a), "l"(b), "l"(c)); return d;
}
__device__ __forceinline__ uint64_t add2(uint64_t a, uint64_t b) {
    uint64_t d; asm("add.rn.f32x2 %0, %1, %2;" : "=l"(d) : "l"(a), "l"(b)); return d;
}
__device__ __forceinline__ uint64_t mul2(uint64_t a, uint64_t b) {
    uint64_t d; asm("mul.rn.f32x2 %0, %1, %2;" : "=l"(d) : "l"(a), "l"(b)); return d;
}

// packed exp(5x): range reduce + quadratic 2^f on [-0.5, 0.5]
__device__ __forceinline__ uint64_t fexp5_2(uint64_t x2) {
    const float KE = 7.2134752044448169f;   // 5 * log2(e)
    const float SH = 12582912.0f;           // 1.5 * 2^23
    const uint64_t KE2 = pk2(KE, KE);
    const uint64_t SH2 = pk2(SH, SH);
    const uint64_t N12 = pk2(-1.0f, -1.0f);
    uint64_t z2 = fma2(x2, KE2, SH2);
    float zl, zh; upk2(z2, zl, zh);
    int e0 = (__float_as_int(zl) - 0x4B3FFF81) << 23;
    int e1 = (__float_as_int(zh) - 0x4B3FFF81) << 23;
    uint64_t nr2 = fma2(z2, N12, SH2);
    uint64_t f2 = fma2(x2, KE2, nr2);
    uint64_t p = pk2(0.24264f, 0.24264f);
    p = fma2(p, f2, pk2(0.70354f, 0.70354f));
    p = fma2(p, f2, pk2(0.99992f, 0.99992f));
    return mul2(p, pk2(__int_as_float(e0), __int_as_float(e1)));
}

// scalar exp(5x), degree-4
__device__ __forceinline__ float fexp5(float x) {
    const float KE = 7.2134752044448169f;
    const float SH = 12582912.0f;
    float z = fmaf(x, KE, SH);
    int   ei = __float_as_int(z);
    float r = z - SH;
    float f = fmaf(x, KE, -r);
    float p = 9.6181291076284771e-3f;
    p = fmaf(p, f, 5.5504108664821580e-2f);
    p = fmaf(p, f, 2.4022650695910071e-1f);
    p = fmaf(p, f, 6.9314718055994531e-1f);
    p = fmaf(p, f, 1.0f);
    return p * __int_as_float((ei - 0x4B400000 + 127) << 23);
}

// ---------------- merged prep + hi/lo conversions (one launch) ----------------
#define SEG_X   2097152
#define SEG_W1F 2162688
#define SEG_W1C 2228224
#define SEG_W2F 2232320
#define SEG_W2C 2240512
#define CONV_BLKS 8752

__global__ void prep_conv_kernel(const float* __restrict__ roi,
                                 const float* __restrict__ w1f, const float* __restrict__ w1c,
                                 const float* __restrict__ w2f, const float* __restrict__ w2c,
                                 const int* __restrict__ lraw, const float* __restrict__ ious) {
    if (blockIdx.x >= CONV_BLKS) {
        int i = (blockIdx.x - CONV_BLKS) * 256 + threadIdx.x;
        bool is64 = true;
        #pragma unroll 1
        for (int p = 0; p < 32; ++p) {
            int lo = lraw[2 * p], hi = lraw[2 * p + 1];
            bool ok = (hi == 0 && lo >= 0) || (hi == -1 && lo < 0);
            if (!ok) { is64 = false; break; }
        }
        int l = is64 ? (int)(((const long long*)lraw)[i]) : lraw[i];
        g_lbl[i] = l;
        g_fgf[i] = (l > 0) ? 1.0f : 0.0f;
        g_vld[i] = (l != -1) ? 1.0f : 0.0f;
        float u = ious[i];
        g_wgt[i] = (u > 0.5f) ? u : 0.0f;
        return;
    }
    int i = blockIdx.x * 256 + threadIdx.x;
    const float* s; __nv_bfloat16 *h, *l; int base;
    if (i < SEG_X)        { s = roi; h = g_Xh;   l = g_Xl;   base = 0; }
    else if (i < SEG_W1F) { s = w1f; h = g_W1fh; l = g_W1fl; base = SEG_X; }
    else if (i < SEG_W1C) { s = w1c; h = g_W1ch; l = g_W1cl; base = SEG_W1F; }
    else if (i < SEG_W2F) { s = w2f; h = g_W2fh; l = g_W2fl; base = SEG_W1C; }
    else                  { s = w2c; h = g_W2ch; l = g_W2cl; base = SEG_W2F; }
    int j = i - base;
    float4 v = ((const float4*)s)[j];
    __nv_bfloat162 h0, h1, l0, l1;
    h0.x = __float2bfloat16(v.x); h0.y = __float2bfloat16(v.y);
    h1.x = __float2bfloat16(v.z); h1.y = __float2bfloat16(v.w);
    l0.x = __float2bfloat16(v.x - __bfloat162float(h0.x));
    l0.y = __float2bfloat16(v.y - __bfloat162float(h0.y));
    l1.x = __float2bfloat16(v.z - __bfloat162float(h1.x));
    l1.y = __float2bfloat16(v.w - __bfloat162float(h1.y));
    ((__nv_bfloat162*)h)[j * 2] = h0; ((__nv_bfloat162*)h)[j * 2 + 1] = h1;
    ((__nv_bfloat162*)l)[j * 2] = l0; ((__nv_bfloat162*)l)[j * 2 + 1] = l1;
}

// ---------------- cp.async bf16 tile loader (BK=64, padded stride 144B) ----------------
__device__ __forceinline__ void ld_tile64(uint32_t dst, const __nv_bfloat16* __restrict__ src,
                                          int rows, int K, int tid) {
    #pragma unroll 4
    for (int i = tid; i < rows * 8; i += 256) {
        int r = i >> 3, c = i & 7;
        asm volatile("cp.async.cg.shared.global [%0], [%1], 16;"
                     :: "r"(dst + r * 144 + c * 16), "l"(src + (size_t)r * K + c * 8) : "memory");
    }
}

// ---------------- layer-1 MMA GEMM (3-chain, single-buffer, occ 2) ----------------
__global__ __launch_bounds__(256, 2) void mma_gemm1(
    const float* __restrict__ bias0, const float* __restrict__ bias1) {
    constexpr int BN = 128, SA = 144;
    constexpr int ATS = 128 * SA;
    constexpr int BTS = BN * SA;
    constexpr int NG = BN / 32, NF = 2 * NG;
    constexpr int N = HD, K = CD;

    extern __shared__ char smem[];
    uint32_t sb = smem_u32(smem);
    const int tid = threadIdx.x, wid = tid >> 5, lane = tid & 31;
    const int wm = wid & 3, wn = wid >> 2;
    const int z = blockIdx.z;
    const int bm = blockIdx.y * 128, bn = blockIdx.x * BN;

    const __nv_bfloat16* Ah = g_Xh;
    const __nv_bfloat16* Al = g_Xl;
    const __nv_bfloat16* Wh = z ? g_W1ch : g_W1fh;
    const __nv_bfloat16* Wl = z ? g_W1cl : g_W1fl;
    const float* bias = z ? bias1 : bias0;
    __nv_bfloat16* oh = z ? g_Hch : g_Hfh;
    __nv_bfloat16* ol = z ? g_Hcl : g_Hfl;

    const int KC = K >> 6;

    float acc[2][NF][4];
    #pragma unroll
    for (int ma = 0; ma < 2; ++ma)
        #pragma unroll
        for (int nf = 0; nf < NF; ++nf)
            #pragma unroll
            for (int e = 0; e < 4; ++e) acc[ma][nf][e] = 0.0f;

    const uint32_t a_off = (uint32_t)((wm * 32 + (lane & 15)) * SA + (lane >> 4) * 16);
    const uint32_t b_off = (uint32_t)((wn * (BN / 2) + ((lane >> 4) << 3) + (lane & 7)) * SA + ((lane >> 3) & 1) * 16);

    for (int kc = 0; kc < KC; ++kc) {
        const int ko = kc * 64;
        if (kc) __syncthreads();
        ld_tile64(sb, Ah + (size_t)bm * K + ko, 128, K, tid);
        ld_tile64(sb + ATS, Al + (size_t)bm * K + ko, 128, K, tid);
        ld_tile64(sb + 2 * ATS, Wh + (size_t)bn * K + ko, BN, K, tid);
        ld_tile64(sb + 2 * ATS + BTS, Wl + (size_t)bn * K + ko, BN, K, tid);
        asm volatile("cp.async.commit_group;" ::: "memory");
        asm volatile("cp.async.wait_group 0;" ::: "memory");
        __syncthreads();

        #pragma unroll
        for (int ks = 0; ks < 4; ++ks) {
            const uint32_t kb = ks * 32;
            uint32_t a_h[2][4], a_l[2][4], b_h[NG][4], b_l[NG][4];
            #pragma unroll
            for (int ma = 0; ma < 2; ++ma) {
                LDSM4(a_h[ma], sb + a_off + ma * 16 * SA + kb);
                LDSM4(a_l[ma], sb + ATS + a_off + ma * 16 * SA + kb);
            }
            #pragma unroll
            for (int g = 0; g < NG; ++g) {
                LDSM4(b_h[g], sb + 2 * ATS + b_off + g * 16 * SA + kb);
                LDSM4(b_l[g], sb + 2 * ATS + BTS + b_off + g * 16 * SA + kb);
            }
            #pragma unroll
            for (int ma = 0; ma < 2; ++ma)
                #pragma unroll
                for (int g = 0; g < NG; ++g) {
                    MMA16816(acc[ma][2 * g],     a_h[ma], b_h[g][0], b_h[g][1]);
                    MMA16816(acc[ma][2 * g + 1], a_h[ma], b_h[g][2], b_h[g][3]);
                    MMA16816(acc[ma][2 * g],     a_h[ma], b_l[g][0], b_l[g][1]);
                    MMA16816(acc[ma][2 * g + 1], a_h[ma], b_l[g][2], b_l[g][3]);
                    MMA16816(acc[ma][2 * g],     a_l[ma], b_h[g][0], b_h[g][1]);
                    MMA16816(acc[ma][2 * g + 1], a_l[ma], b_h[g][2], b_h[g][3]);
                }
        }
    }

    #pragma unroll
    for (int ma = 0; ma < 2; ++ma)
        #pragma unroll
        for (int nf = 0; nf < NF; ++nf)
            #pragma unroll
            for (int rp = 0; rp < 2; ++rp) {
                const int r = bm + wm * 32 + ma * 16 + rp * 8 + (lane >> 2);
                const int c = bn + wn * (BN / 2) + nf * 8 + (lane & 3) * 2;
                float2 bb = *(const float2*)(bias + c);
                float v0 = fmaxf(acc[ma][nf][rp * 2 + 0] + bb.x, 0.0f);
                float v1 = fmaxf(acc[ma][nf][rp * 2 + 1] + bb.y, 0.0f);
                __nv_bfloat162 hv, lv;
                hv.x = __float2bfloat16(v0); hv.y = __float2bfloat16(v1);
                lv.x = __float2bfloat16(v0 - __bfloat162float(hv.x));
                lv.y = __float2bfloat16(v1 - __bfloat162float(hv.y));
                *(__nv_bfloat162*)(oh + (size_t)r * N + c) = hv;
                *(__nv_bfloat162*)(ol + (size_t)r * N + c) = lv;
            }
}

// ---------------- layer-2 body: single-buffer GEMM + fused normalize + hi-split + eii/ss ----------------
template<int BN>
__device__ __forceinline__ void gemm2_body(
    const __nv_bfloat16* __restrict__ Ah, const __nv_bfloat16* __restrict__ Al,
    const __nv_bfloat16* __restrict__ Wh, const __nv_bfloat16* __restrict__ Wl,
    const float* __restrict__ bias,
    float* __restrict__ Zout, __nv_bfloat16* __restrict__ Oh,
    float* __restrict__ eii, float* __restrict__ ssout,
    int bm, char* smem) {
    constexpr int SA = 144;
    constexpr int ATS = 128 * SA;
    constexpr int BTS = BN * SA;
    constexpr int NG = BN / 32, NF = 2 * NG;
    constexpr int K = HD;
    constexpr int ZS = BN + 4;

    uint32_t sb = smem_u32(smem);
    float* zbuf = (float*)smem;
    const int tid = threadIdx.x, wid = tid >> 5, lane = tid & 31;
    const int wm = wid & 3, wn = wid >> 2;

    const int KC = K >> 6;

    float acc[2][NF][4];
    #pragma unroll
    for (int ma = 0; ma < 2; ++ma)
        #pragma unroll
        for (int nf = 0; nf < NF; ++nf)
            #pragma unroll
            for (int e = 0; e < 4; ++e) acc[ma][nf][e] = 0.0f;

    const uint32_t a_off = (uint32_t)((wm * 32 + (lane & 15)) * SA + (lane >> 4) * 16);
    const uint32_t b_off = (uint32_t)((wn * (BN / 2) + ((lane >> 4) << 3) + (lane & 7)) * SA + ((lane >> 3) & 1) * 16);

    for (int kc = 0; kc < KC; ++kc) {
        const int ko = kc * 64;
        if (kc) __syncthreads();
        ld_tile64(sb, Ah + (size_t)bm * K + ko, 128, K, tid);
        ld_tile64(sb + ATS, Al + (size_t)bm * K + ko, 128, K, tid);
        ld_tile64(sb + 2 * ATS, Wh + ko, BN, K, tid);
        ld_tile64(sb + 2 * ATS + BTS, Wl + ko, BN, K, tid);
        asm volatile("cp.async.commit_group;" ::: "memory");
        asm volatile("cp.async.wait_group 0;" ::: "memory");
        __syncthreads();

        #pragma unroll
        for (int ks = 0; ks < 4; ++ks) {
            const uint32_t kb = ks * 32;
            uint32_t a_h[2][4], a_l[2][4], b_h[NG][4], b_l[NG][4];
            #pragma unroll
            for (int ma = 0; ma < 2; ++ma) {
                LDSM4(a_h[ma], sb + a_off + ma * 16 * SA + kb);
                LDSM4(a_l[ma], sb + ATS + a_off + ma * 16 * SA + kb);
            }
            #pragma unroll
            for (int g = 0; g < NG; ++g) {
                LDSM4(b_h[g], sb + 2 * ATS + b_off + g * 16 * SA + kb);
                LDSM4(b_l[g], sb + 2 * ATS + BTS + b_off + g * 16 * SA + kb);
            }
            #pragma unroll
            for (int ma = 0; ma < 2; ++ma)
                #pragma unroll
                for (int g = 0; g < NG; ++g) {
                    MMA16816(acc[ma][2 * g],     a_h[ma], b_h[g][0], b_h[g][1]);
                    MMA16816(acc[ma][2 * g + 1], a_h[ma], b_h[g][2], b_h[g][3]);
                    MMA16816(acc[ma][2 * g],     a_h[ma], b_l[g][0], b_l[g][1]);
                    MMA16816(acc[ma][2 * g + 1], a_h[ma], b_l[g][2], b_l[g][3]);
                    MMA16816(acc[ma][2 * g],     a_l[ma], b_h[g][0], b_h[g][1]);
                    MMA16816(acc[ma][2 * g + 1], a_l[ma], b_h[g][2], b_h[g][3]);
                }
        }
    }
    __syncthreads();

    #pragma unroll
    for (int ma = 0; ma < 2; ++ma)
        #pragma unroll
        for (int nf = 0; nf < NF; ++nf)
            #pragma unroll
            for (int rp = 0; rp < 2; ++rp) {
                const int r = wm * 32 + ma * 16 + rp * 8 + (lane >> 2);
                const int c = wn * (BN / 2) + nf * 8 + (lane & 3) * 2;
                float2 bb = *(const float2*)(bias + c);
                zbuf[r * ZS + c] = acc[ma][nf][rp * 2 + 0] + bb.x;
                zbuf[r * ZS + c + 1] = acc[ma][nf][rp * 2 + 1] + bb.y;
            }
    __syncthreads();

    constexpr int CE = BN / 32;
    for (int rr = 0; rr < 16; ++rr) {
        const int r = wid * 16 + rr;
        const int grow = bm + r;
        float v[CE];
        float ss = 0.0f;
        #pragma unroll
        for (int q = 0; q < CE; ++q) { v[q] = zbuf[r * ZS + lane + q * 32]; ss += v[q] * v[q]; }
        #pragma unroll
        for (int o = 16; o; o >>= 1) ss += __shfl_xor_sync(0xffffffffu, ss, o);
        const float inv = 1.0f / fmaxf(sqrtf(ss), 1e-8f);
        float hh = 0.0f;
        #pragma unroll
        for (int q = 0; q < CE; ++q) {
            float zv = v[q] * inv;
            if (Zout) Zout[(size_t)grow * BN + lane + q * 32] = zv;
            __nv_bfloat16 h = __float2bfloat16(zv);
            Oh[(size_t)grow * BN + lane + q * 32] = h;
            float hf = __bfloat162float(h);
            hh = fmaf(hf, hf, hh);
        }
        #pragma unroll
        for (int o = 16; o; o >>= 1) hh += __shfl_xor_sync(0xffffffffu, hh, o);
        if (lane == 0) {
            eii[grow] = fexp5(hh);
            if (ssout) ssout[grow] = ss * inv * inv;
        }
    }
}

__global__ __launch_bounds__(256, 2) void mma_gemm2_all(
    const float* __restrict__ b2f, const float* __restrict__ b2c) {
    extern __shared__ char smem[];
    if (blockIdx.x < 64)
        gemm2_body<FGDIM>(g_Hfh, g_Hfl, g_W2fh, g_W2fl, b2f,
                          nullptr, g_Zfh, g_eiif, nullptr,
                          blockIdx.x * 128, smem);
    else
        gemm2_body<CLDIM>(g_Hch, g_Hcl, g_W2ch, g_W2cl, b2c,
                          g_Zc, g_Zch, g_eiic, g_ssc,
                          (blockIdx.x - 64) * 128, smem);
}

// ---------------- per-class z sums: batch-4 prefetch row-pass ----------------
__global__ void class_sum1_kernel() {
    __shared__ float sh[20][CLDIM];
    const int d = threadIdx.x;
    #pragma unroll
    for (int c = 0; c < 20; ++c) sh[c][d] = 0.0f;
    const int i0 = blockIdx.x * (NR / CSBLK);
    constexpr int NB = (NR / CSBLK) / 4;
    int   lc[4];
    float vc[4];
    #pragma unroll
    for (int k = 0; k < 4; ++k) {
        lc[k] = g_lbl[i0 + k];
        vc[k] = g_Zc[(size_t)(i0 + k) * CLDIM + d];
    }
    #pragma unroll 1
    for (int b = 0; b < NB; ++b) {
        int   ln[4];
        float vn[4];
        if (b + 1 < NB) {
            const int ib = i0 + (b + 1) * 4;
            #pragma unroll
            for (int k = 0; k < 4; ++k) {
                ln[k] = g_lbl[ib + k];
                vn[k] = g_Zc[(size_t)(ib + k) * CLDIM + d];
            }
        }
        #pragma unroll
        for (int k = 0; k < 4; ++k)
            if (lc[k] > 0) sh[lc[k] - 1][d] += vc[k];
        #pragma unroll
        for (int k = 0; k < 4; ++k) { lc[k] = ln[k]; vc[k] = vn[k]; }
    }
    #pragma unroll
    for (int c = 0; c < 20; ++c)
        g_Sp[((size_t)c * CSBLK + blockIdx.x) * CLDIM + d] = sh[c][d];
}
__global__ void class_sum2_kernel() {
    float s = 0.0f;
    #pragma unroll 8
    for (int g = 0; g < CSBLK; ++g)
        s += g_Sp[((size_t)blockIdx.x * CSBLK + g) * CLDIM + threadIdx.x];
    g_S[blockIdx.x * CLDIM + threadIdx.x] = s;
}

// ---------------- per-row sum_pos for CLS (warp per row) ----------------
__global__ void row_sp_kernel() {
    int row = blockIdx.x * 8 + (threadIdx.x >> 5);
    int lane = threadIdx.x & 31;
    int l = g_lbl[row];
    const float* S = g_S + (l > 0 ? (l - 1) : 0) * CLDIM;
    float sd = 0.0f;
    #pragma unroll
    for (int c = lane; c < CLDIM; c += 32)
        sd += g_Zc[(size_t)row * CLDIM + c] * S[c];
    #pragma unroll
    for (int o = 16; o; o >>= 1) sd += __shfl_xor_sync(0xffffffffu, sd, o);
    if (lane == 0) g_sp[row] = 5.0f * (sd - g_ssc[row]);
}

// ---------------- cp.async tile loader for sim (full K resident) ----------------
template<int KD>
__device__ __forceinline__ void load_tile(uint32_t dst, const __nv_bfloat16* __restrict__ src, int tid) {
    constexpr int CPR = KD / 8;
    constexpr int SA = KD * 2 + 16;
    #pragma unroll
    for (int i = tid; i < 128 * CPR; i += 256) {
        int r = i / CPR, c = i % CPR;
        asm volatile("cp.async.cg.shared.global [%0], [%1], 16;"
                     :: "r"(dst + r * SA + c * 16), "l"(src + (size_t)r * KD + c * 8) : "memory");
    }
}

// ---------------- sim body (1-chain hi*hi, flag-load packed epilogue) ----------------
template<int KD, bool CLS, int NSPLT>
__device__ __forceinline__ void sim_body(int bx, int by, char* smem) {
    constexpr int SA = KD * 2 + 16;
    constexpr int TSZ = 128 * SA;
    constexpr int SLAB = NR / NSPLT;
    constexpr int TCOLS = SLAB / 128;
    constexpr int KSTEPS = KD / 16;
    constexpr int B_OFF = TSZ;

    uint32_t sb = smem_u32(smem);
    const int tid = threadIdx.x, wid = tid >> 5, lane = tid & 31;
    const int wm = wid & 3, wn = wid >> 2;
    const int bm = bx * 128;
    const int c0 = by * SLAB;
    const __nv_bfloat16* Zh = CLS ? g_Zch : g_Zfh;
    const float* flg = CLS ? g_vld : g_fgf;

    load_tile<KD>(sb, Zh + (size_t)bm * KD, tid);
    load_tile<KD>(sb + B_OFF, Zh + (size_t)c0 * KD, tid);
    asm volatile("cp.async.commit_group;" ::: "memory");

    uint64_t dn2[2][2] = {{0ull, 0ull}, {0ull, 0ull}};
    uint64_t x12[2][2] = {{0ull, 0ull}, {0ull, 0ull}};

    const uint32_t a_off = (uint32_t)((wm * 32 + (lane & 15)) * SA + (lane >> 4) * 16);
    const uint32_t b_off = (uint32_t)((wn * 64 + ((lane >> 4) << 3) + (lane & 7)) * SA + ((lane >> 3) & 1) * 16);

    float acc[2][8][4];
    #pragma unroll
    for (int ma = 0; ma < 2; ++ma)
        #pragma unroll
        for (int na = 0; na < 8; ++na)
            #pragma unroll
            for (int e = 0; e < 4; ++e) acc[ma][na][e] = 0.0f;

    asm volatile("cp.async.wait_group 0;" ::: "memory");
    __syncthreads();

    for (int t = 0; t < TCOLS; ++t) {
        const uint32_t bcur = sb + B_OFF + (t & 1) * TSZ;
        if (t + 1 < TCOLS) {
            load_tile<KD>(sb + B_OFF + ((t + 1) & 1) * TSZ,
                          Zh + (size_t)(c0 + (t + 1) * 128) * KD, tid);
            asm volatile("cp.async.commit_group;" ::: "memory");
        }

        #pragma unroll
        for (int ks = 0; ks < KSTEPS; ++ks) {
            uint32_t a_h[2][4], b_h[4][4];
            const uint32_t kb = ks * 32;
            #pragma unroll
            for (int ma = 0; ma < 2; ++ma)
                LDSM4(a_h[ma], sb + a_off + ma * 16 * SA + kb);
            #pragma unroll
            for (int g = 0; g < 4; ++g)
                LDSM4(b_h[g], bcur + b_off + g * 16 * SA + kb);
            #pragma unroll
            for (int ma = 0; ma < 2; ++ma)
                #pragma unroll
                for (int g = 0; g < 4; ++g) {
                    MMA16816(acc[ma][2 * g],     a_h[ma], b_h[g][0], b_h[g][1]);
                    MMA16816(acc[ma][2 * g + 1], a_h[ma], b_h[g][2], b_h[g][3]);
                }
        }

        const int tb = c0 + t * 128;
        #pragma unroll
        for (int na = 0; na < 8; ++na) {
            const int cA = wn * 64 + na * 8 + (lane & 3) * 2;
            const float2 lp = *(const float2*)(flg + tb + cA);
            const uint64_t fl2 = pk2(lp.x, lp.y);
            #pragma unroll
            for (int ma = 0; ma < 2; ++ma) {
                float* c = acc[ma][na];
                uint64_t ea = fexp5_2(pk2(c[0], c[1]));
                uint64_t eb = fexp5_2(pk2(c[2], c[3]));
                if (CLS) {
                    dn2[ma][0] = fma2(ea, fl2, dn2[ma][0]);
                    dn2[ma][1] = fma2(eb, fl2, dn2[ma][1]);
                } else {
                    dn2[ma][0] = add2(dn2[ma][0], ea);
                    dn2[ma][1] = add2(dn2[ma][1], eb);
                    x12[ma][0] = fma2(ea, fl2, x12[ma][0]);
                    x12[ma][1] = fma2(eb, fl2, x12[ma][1]);
                }
                c[0] = 0.0f; c[1] = 0.0f; c[2] = 0.0f; c[3] = 0.0f;
            }
        }

        if (t + 1 < TCOLS) {
            asm volatile("cp.async.wait_group 0;" ::: "memory");
        }
        __syncthreads();
    }

    float dn[2][2], x1[2][2];
    #pragma unroll
    for (int ma = 0; ma < 2; ++ma)
        #pragma unroll
        for (int rp = 0; rp < 2; ++rp) {
            float a, b;
            upk2(dn2[ma][rp], a, b); dn[ma][rp] = a + b;
            upk2(x12[ma][rp], a, b); x1[ma][rp] = a + b;
            #pragma unroll
            for (int o = 1; o <= 2; o <<= 1) {
                dn[ma][rp] += __shfl_xor_sync(0xffffffffu, dn[ma][rp], o);
                if (!CLS) x1[ma][rp] += __shfl_xor_sync(0xffffffffu, x1[ma][rp], o);
            }
        }

    float* red = (float*)smem;
    __syncthreads();
    if (wn == 1 && (lane & 3) == 0) {
        #pragma unroll
        for (int ma = 0; ma < 2; ++ma)
            #pragma unroll
            for (int rp = 0; rp < 2; ++rp) {
                int rl = wm * 32 + ma * 16 + rp * 8 + (lane >> 2);
                red[rl * 2 + 0] = dn[ma][rp];
                red[rl * 2 + 1] = x1[ma][rp];
            }
    }
    __syncthreads();
    if (wn == 0 && (lane & 3) == 0) {
        const int s = by;
        #pragma unroll
        for (int ma = 0; ma < 2; ++ma)
            #pragma unroll
            for (int rp = 0; rp < 2; ++rp) {
                int rl = wm * 32 + ma * 16 + rp * 8 + (lane >> 2);
                float a = dn[ma][rp] + red[rl * 2 + 0];
                int g = bm + rl;
                if (CLS) {
                    g_pcl[(size_t)s * NR + g] = a;
                } else {
                    float b = x1[ma][rp] + red[rl * 2 + 1];
                    g_pfg[((size_t)s * NR + g) * 2 + 0] = a;
                    g_pfg[((size_t)s * NR + g) * 2 + 1] = b;
                }
            }
    }
}

__global__ __launch_bounds__(256, 2) void sim_all_kernel() {
    extern __shared__ char smem[];
    if (blockIdx.x < 64 * NSPL_CLS) {
        sim_body<CLDIM, true, NSPL_CLS>(blockIdx.x >> 2, blockIdx.x & 3, smem);
    } else {
        const int b = blockIdx.x - 64 * NSPL_CLS;
        sim_body<FGDIM, false, NSPL_FG>(b >> 2, b & 3, smem);
    }
}

// ---------------- final deterministic reduction ----------------
__global__ void finalize_kernel(float* __restrict__ out) {
    __shared__ int hist[22];
    __shared__ float red[256][4];
    int tid = threadIdx.x;
    if (tid < 22) hist[tid] = 0;
    __syncthreads();
    for (int i = tid; i < NR; i += 256) atomicAdd(&hist[g_lbl[i] + 1], 1);
    __syncthreads();
    int nnon = NR - hist[0];
    int nfgset = nnon - hist[1];
    float nfg = 0.0f, dfg = 0.0f, ncl = 0.0f, dcl = 0.0f;
    for (int i = tid; i < NR; i += 256) {
        int l = g_lbl[i];
        if (l > 0) {
            float w = g_wgt[i];
            float dnv = 0.0f, nm = 0.0f;
            #pragma unroll
            for (int s = 0; s < NSPL_FG; ++s) {
                dnv += g_pfg[((size_t)s * NR + i) * 2 + 0];
                nm  += g_pfg[((size_t)s * NR + i) * 2 + 1];
            }
            float ef = g_eiif[i];
            dnv -= ef; nm -= ef;
            if (nfgset - 1 > 0) {
                float li = -logf((nm + 1e-8f) / (dnv + 1e-8f));
                nfg += li * w; dfg += w;
            }
            float dc = 0.0f;
            #pragma unroll
            for (int s = 0; s < NSPL_CLS; ++s)
                dc += g_pcl[(size_t)s * NR + i];
            dc -= g_eiic[i];
            float np = (float)(hist[l + 1] - 1);
            if (np > 0.5f && (nnon - 1) > 0) {
                float li = -(g_sp[i] - np * logf(dc)) / np;
                ncl += li * w; dcl += w;
            }
        }
    }
    red[tid][0] = nfg; red[tid][1] = dfg; red[tid][2] = ncl; red[tid][3] = dcl;
    __syncthreads();
    for (int s = 128; s > 0; s >>= 1) {
        if (tid < s) {
            red[tid][0] += red[tid + s][0]; red[tid][1] += red[tid + s][1];
            red[tid][2] += red[tid + s][2]; red[tid][3] += red[tid + s][3];
        }
        __syncthreads();
    }
    if (tid == 0) {
        out[0] = red[0][0] / (red[0][1] + 1e-8f);
        out[1] = red[0][2] / (red[0][3] + 1e-12f);
    }
}

// ---------------- launch (fork class chain concurrent with sims) ----------------
extern "C" void kernel_launch(void* const* d_in, const int* in_sizes, int n_in,
                              void* d_out, int out_size) {
    const float* roi = (const float*)d_in[0];
    const int*   lab = (const int*)d_in[1];
    const float* iou = (const float*)d_in[2];
    const float* w1f = (const float*)d_in[3];
    const float* b1f = (const float*)d_in[4];
    const float* w2f = (const float*)d_in[5];
    const float* b2f = (const float*)d_in[6];
    const float* w1c = (const float*)d_in[7];
    const float* b1c = (const float*)d_in[8];
    const float* w2c = (const float*)d_in[9];
    const float* b2c = (const float*)d_in[10];

    constexpr int SM_G1 = 2 * 128 * 144 + 2 * 128 * 144;   // 73728, single stage → occ 2
    constexpr int SMEM_SIM = 3 * 128 * (CLDIM * 2 + 16);   // 104448
    cudaFuncSetAttribute(mma_gemm1,      cudaFuncAttributeMaxDynamicSharedMemorySize, SM_G1);
    cudaFuncSetAttribute(mma_gemm2_all,  cudaFuncAttributeMaxDynamicSharedMemorySize, SM_G1);
    cudaFuncSetAttribute(sim_all_kernel, cudaFuncAttributeMaxDynamicSharedMemorySize, SMEM_SIM);

    cudaStream_t s2;
    cudaStreamCreateWithFlags(&s2, cudaStreamNonBlocking);
    cudaEvent_t evFork, evJoin;
    cudaEventCreateWithFlags(&evFork, cudaEventDisableTiming);
    cudaEventCreateWithFlags(&evJoin, cudaEventDisableTiming);

    prep_conv_kernel<<<CONV_BLKS + NR / 256, 256>>>(roi, w1f, w1c, w2f, w2c, lab, iou);

    mma_gemm1<<<dim3(HD / 128, NR / 128, 2), 256, SM_G1>>>(b1f, b1c);

    mma_gemm2_all<<<128, 256, SM_G1>>>(b2f, b2c);

    // fork: class chain on side stream, sims on main stream (independent work)
    cudaEventRecord(evFork, 0);
    cudaStreamWaitEvent(s2, evFork, 0);
    class_sum1_kernel<<<CSBLK, CLDIM, 0, s2>>>();
    class_sum2_kernel<<<20, CLDIM, 0, s2>>>();
    row_sp_kernel<<<NR / 8, 256, 0, s2>>>();
    cudaEventRecord(evJoin, s2);

    sim_all_kernel<<<64 * NSPL_CLS + 64 * NSPL_FG, 256, SMEM_SIM>>>();

    // join before finalize
    cudaStreamWaitEvent(0, evJoin, 0);
    finalize_kernel<<<1, 256>>>((float*)d_out);
}